// round 13
// baseline (speedup 1.0000x reference)
#include <cuda_runtime.h>
#include <cuda_bf16.h>
#include <cstdint>

#define BB   256
#define PP   196
#define ENC  2048
#define VV   10000
#define VVP  10112
#define EE   512
#define HH   512
#define AA   512
#define SS   54
#define TT   53
#define KG   2560
#define KGX  3072
#define NBIG (KG + VVP)          // 12672
#define OUT_PRED_OFF (BB + BB*SS)
#define NSPLITK 4
#define STAGE_B 24576
#define SMEM_DYN (3*STAGE_B)

__device__ int   g_order[BB];
__device__ int   g_predlen[BB];
__device__ int   g_caps[BB*SS];
__device__ float g_bias_gates[4*HH];
__device__ float g_bias_big[NBIG];
__device__ float g_c[BB*HH];
__device__ float g_hidatt[BB*AA];
__device__ float g_gs[BB*ENC];
__device__ float g_alpha[BB*PP];
__device__ float g_gpart[NSPLITK][BB*4*HH];

// tiled bf16 hi/lo images (hi plane then lo plane), 8x8 tiles of 128B
#define PE_WG   ((size_t)(4*HH)*KGX)
#define PE_BIG  ((size_t)NBIG*HH)
#define PE_AE   ((size_t)AA*ENC)
#define PE_EH   ((size_t)HH*ENC)
#define PE_IMG  ((size_t)BB*PP*ENC)
#define PE_MEAN ((size_t)BB*ENC)
#define PE_H    ((size_t)BB*HH)
#define PE_GIN  ((size_t)BB*KGX)

__device__ __align__(128) uint16_t g_Wgt  [2*PE_WG];
__device__ __align__(128) uint16_t g_bigw [2*PE_BIG];
__device__ __align__(128) uint16_t g_aet  [2*PE_AE];
__device__ __align__(128) uint16_t g_eht  [2*PE_EH];
__device__ __align__(128) uint16_t g_ect  [2*PE_EH];
__device__ __align__(128) uint16_t g_imgt [2*PE_IMG];    // 411 MB
__device__ __align__(128) uint16_t g_meani[2*PE_MEAN];
__device__ __align__(128) uint16_t g_himg [2*PE_H];
__device__ __align__(128) uint16_t g_gint [2*PE_GIN];
__device__ __align__(16)  __nv_bfloat16 g_img16[PE_IMG];
__device__ __align__(16)  __nv_bfloat16 g_encatt16[(size_t)BB*PP*AA];

__device__ __forceinline__ float sigf(float x) { return 1.f / (1.f + expf(-x)); }

__device__ __forceinline__ void cvt2(float x, float y, uint32_t& hi, uint32_t& lo) {
    __nv_bfloat162 h = __floats2bfloat162_rn(x, y);
    float rx = x - __bfloat162float(h.x);
    float ry = y - __bfloat162float(h.y);
    __nv_bfloat162 l = __floats2bfloat162_rn(rx, ry);
    hi = *(uint32_t*)&h;
    lo = *(uint32_t*)&l;
}

__device__ __forceinline__ size_t ioff32(int n, int k, int Kd) {
    return ((size_t)(n >> 3) * (Kd >> 3) + (k >> 3)) * 32 + (n & 7) * 4 + ((k & 7) >> 1);
}

__device__ __forceinline__ uint32_t smem_u32(const void* p) {
    uint32_t a;
    asm("{ .reg .u64 t; cvta.to.shared.u64 t, %1; cvt.u32.u64 %0, t; }" : "=r"(a) : "l"(p));
    return a;
}

__device__ __forceinline__ void mma_bf16(float4& d, const uint32_t a[4], const uint32_t b[2]) {
    asm volatile(
        "mma.sync.aligned.m16n8k16.row.col.f32.bf16.bf16.f32 "
        "{%0,%1,%2,%3}, {%4,%5,%6,%7}, {%8,%9}, {%0,%1,%2,%3};\n"
        : "+f"(d.x), "+f"(d.y), "+f"(d.z), "+f"(d.w)
        : "r"(a[0]), "r"(a[1]), "r"(a[2]), "r"(a[3]), "r"(b[0]), "r"(b[1]));
}

__device__ __forceinline__ void ldsm4(uint32_t r[4], uint32_t addr) {
    asm volatile("ldmatrix.sync.aligned.m8n8.x4.shared.b16 {%0,%1,%2,%3}, [%4];"
        : "=r"(r[0]), "=r"(r[1]), "=r"(r[2]), "=r"(r[3]) : "r"(addr));
}

// ---------------- setup ----------------
__global__ void setup_kernel(const int* __restrict__ caps32,
                             const int* __restrict__ lens32,
                             const float* __restrict__ b_ih,
                             const float* __restrict__ b_hh,
                             const float* __restrict__ ah_b,
                             const float* __restrict__ sag_b,
                             const float* __restrict__ fc_b,
                             float* __restrict__ out)
{
    __shared__ int s_order[BB];
    __shared__ int s_is64;
    int tid = threadIdx.x;
    if (tid == 0) {
        int is64 = (lens32[1] == 0 && lens32[3] == 0 && lens32[5] == 0) ? 1 : 0;
        s_is64 = is64;
        int cnt[64];
        for (int i = 0; i < 64; i++) cnt[i] = 0;
        for (int i = 0; i < BB; i++) {
            int l = is64 ? lens32[2*i] : lens32[i];
            cnt[max(0, min(63, l))]++;
        }
        int start[64]; int run = 0;
        for (int l = 63; l >= 0; l--) { start[l] = run; run += cnt[l]; }
        for (int i = 0; i < BB; i++) {
            int l = is64 ? lens32[2*i] : lens32[i];
            s_order[start[max(0, min(63, l))]++] = i;
        }
    }
    __syncthreads();
    int is64 = s_is64;
    int b = tid;
    int ord = s_order[b];
    g_order[b] = ord;
    int len = is64 ? lens32[2*ord] : lens32[ord];
    len = max(1, min(SS, len));
    g_predlen[b] = len - 1;
    out[b] = (float)(len - 1);
    for (int s = 0; s < SS; s++) {
        size_t idx = (size_t)ord * SS + s;
        int cap = is64 ? caps32[2*idx] : caps32[idx];
        out[BB + b*SS + s] = (float)cap;
        g_caps[b*SS + s] = max(0, min(VV - 1, cap));
    }
    for (int j = tid; j < 4*HH; j += BB) g_bias_gates[j] = b_ih[j] + b_hh[j];
    for (int j = tid; j < NBIG; j += BB) {
        float v;
        if      (j < AA)      v = ah_b[j];
        else if (j < KG)      v = sag_b[j - AA];
        else if (j < KG + VV) v = fc_b[j - KG];
        else                  v = 0.f;
        g_bias_big[j] = v;
    }
}

// ---------------- single build kernel: all weight + img images ----------------
#define GRID_BUILD 68480
__global__ void build_all(const float* __restrict__ W_ih, const float* __restrict__ W_hh,
                          const float* __restrict__ ah_w, const float* __restrict__ sag_w,
                          const float* __restrict__ fc_w, const float* __restrict__ ae_w,
                          const float* __restrict__ eh_w, const float* __restrict__ ec_w,
                          const float* __restrict__ img)
{
    int bid = blockIdx.x;
    const float* s = nullptr;
    uint16_t* dimg; size_t pe; int n, Ks, koff, Kd; bool flat = false;

    if (bid < 2048)      { s = W_ih + (size_t)bid*KG;  dimg = g_Wgt;  pe = PE_WG;  n = bid;    Ks = KG;  koff = 0;  Kd = KGX; }
    else if (bid < 4096) { int i = bid-2048;  s = W_hh + (size_t)i*HH;  dimg = g_Wgt;  pe = PE_WG;  n = i;       Ks = HH;  koff = KG; Kd = KGX; }
    else if (bid < 4608) { int i = bid-4096;  s = ah_w + (size_t)i*HH;  dimg = g_bigw; pe = PE_BIG; n = i;       Ks = HH;  koff = 0;  Kd = HH;  }
    else if (bid < 6656) { int i = bid-4608;  s = sag_w + (size_t)i*HH; dimg = g_bigw; pe = PE_BIG; n = AA+i;    Ks = HH;  koff = 0;  Kd = HH;  }
    else if (bid < 16656){ int i = bid-6656;  s = fc_w + (size_t)i*HH;  dimg = g_bigw; pe = PE_BIG; n = KG+i;    Ks = HH;  koff = 0;  Kd = HH;  }
    else if (bid < 16768){ int i = bid-16656; s = nullptr;              dimg = g_bigw; pe = PE_BIG; n = KG+VV+i; Ks = HH;  koff = 0;  Kd = HH;  }
    else if (bid < 17280){ int i = bid-16768; s = ae_w + (size_t)i*ENC; dimg = g_aet;  pe = PE_AE;  n = i;       Ks = ENC; koff = 0;  Kd = ENC; }
    else if (bid < 17792){ int i = bid-17280; s = eh_w + (size_t)i*ENC; dimg = g_eht;  pe = PE_EH;  n = i;       Ks = ENC; koff = 0;  Kd = ENC; }
    else if (bid < 18304){ int i = bid-17792; s = ec_w + (size_t)i*ENC; dimg = g_ect;  pe = PE_EH;  n = i;       Ks = ENC; koff = 0;  Kd = ENC; }
    else                 { int i = bid-18304; s = img + (size_t)i*ENC;  dimg = g_imgt; pe = PE_IMG; n = i;       Ks = ENC; koff = 0;  Kd = ENC; flat = true; }

    uint32_t* d32 = (uint32_t*)dimg;
    size_t p32 = pe >> 1;
    for (int p = threadIdx.x; p < Ks/2; p += 256) {
        int k = 2*p;
        float v0 = 0.f, v1 = 0.f;
        if (s) { float2 vv = *(const float2*)(s + k); v0 = vv.x; v1 = vv.y; }
        uint32_t hi, lo;
        cvt2(v0, v1, hi, lo);
        size_t off = ioff32(n, koff + k, Kd);
        d32[off]       = hi;
        d32[p32 + off] = lo;
        if (flat) ((uint32_t*)g_img16)[((size_t)n*ENC + k) >> 1] = hi;
    }
}

// ---------------- mean over pixels -> tiled mean image ----------------
__global__ void mean_kernel(const float* __restrict__ img)
{
    int b  = blockIdx.y;
    int ch = (blockIdx.x * 256 + threadIdx.x) * 2;
    int ord = g_order[b];
    const float2* base = (const float2*)(img + (size_t)ord * PP * ENC) + (ch >> 1);
    float a0 = 0.f, a1 = 0.f;
#pragma unroll 4
    for (int p = 0; p < PP; p++) { float2 v = base[(size_t)p * (ENC/2)]; a0 += v.x; a1 += v.y; }
    a0 *= (1.0f / (float)PP);
    a1 *= (1.0f / (float)PP);
    uint32_t hi, lo;
    cvt2(a0, a1, hi, lo);
    size_t off = ioff32(b, ch, ENC);
    ((uint32_t*)g_meani)[off]             = hi;
    ((uint32_t*)g_meani)[(PE_MEAN>>1)+off]= lo;
}

// ================= bf16 x2/x3 HMMA GEMM: all-cp.async fills, 3-stage ==========
#define M_PLAIN   0
#define M_BIG     1
#define M_LOGITS  2
#define M_PLAIN16 3
#define M_H0      4

template<int NSP, int MODE, bool MASKED>
__global__ void __launch_bounds__(256)
kmma(const uint16_t* __restrict__ At, int Ka, size_t pA,
     const uint16_t* __restrict__ Wt, int Kw, size_t pW,
     const float* __restrict__ bias, float* __restrict__ C,
     int M, int N, int Klen, int t,
     float* __restrict__ out2, float* __restrict__ out3)
{
    extern __shared__ __align__(16) char smd[];
    const int m0 = blockIdx.y * 64;
    const int n0 = blockIdx.x * 128;
    if (MASKED && g_predlen[m0] <= t) return;
    if (MODE == M_BIG) {
        if (n0 < KG) { if (g_predlen[m0] <= t) return; }
        else         { if (t == 0 || g_predlen[m0] <= t - 1) return; }
    }
    const int kbase = blockIdx.z * Klen;
    if (gridDim.z > 1) C += (size_t)blockIdx.z * M * N;

    const int tid  = threadIdx.x;
    const int lane = tid & 31;
    const int w    = tid >> 5;
    const int wm   = (w & 1) * 32;
    const int wn   = (w >> 1) * 32;
    const int r    = lane >> 2;
    const int c    = lane & 3;
    const int g8   = lane >> 3;
    const int r8   = lane & 7;
    const uint32_t sbase = smem_u32(smd);

    const int a_mt = tid >> 5, a_kt = (tid >> 3) & 3, a_rw = tid & 7;

    float4 acc[2][4];
#pragma unroll
    for (int i = 0; i < 2; i++)
#pragma unroll
        for (int j = 0; j < 4; j++) acc[i][j] = make_float4(0.f, 0.f, 0.f, 0.f);

    auto fill = [&](int s, int buf) {
        int k0 = kbase + s * 32;
        uint32_t sreg = sbase + (uint32_t)buf * STAGE_B;
        {
            size_t tile = (size_t)((m0 >> 3) + a_mt) * (Ka >> 3) + ((k0 >> 3) + a_kt);
            uint32_t so = sreg + (uint32_t)((a_mt * 4 + a_kt) * 128 + a_rw * 16);
            const char* g = (const char*)At + tile * 128 + a_rw * 16;
            asm volatile("cp.async.cg.shared.global [%0], [%1], 16;" :: "r"(so), "l"(g));
            asm volatile("cp.async.cg.shared.global [%0], [%1], 16;"
                         :: "r"(so + 4096), "l"(g + pA * 2));
        }
#pragma unroll
        for (int i = 0; i < (NSP == 3 ? 4 : 2); i++) {
            int plane = i >> 1, half = i & 1;
            int uu = tid + half * 256;
            int nt = uu >> 5, kt = (uu >> 3) & 3, rw = uu & 7;
            size_t tile = (size_t)((n0 >> 3) + nt) * (Kw >> 3) + ((k0 >> 3) + kt);
            const char* g = (const char*)Wt + (size_t)plane * pW * 2 + tile * 128 + rw * 16;
            uint32_t so = sreg + 8192 + (uint32_t)(plane * 8192 + (nt * 4 + kt) * 128 + rw * 16);
            asm volatile("cp.async.cg.shared.global [%0], [%1], 16;" :: "r"(so), "l"(g));
        }
        asm volatile("cp.async.commit_group;" ::: "memory");
    };

    const int nst = Klen / 32;
    fill(0, 0);
    fill(1, 1);
    for (int s = 0; s < nst; s++) {
        if (s + 1 < nst) asm volatile("cp.async.wait_group 1;" ::: "memory");
        else             asm volatile("cp.async.wait_group 0;" ::: "memory");
        __syncthreads();
        if (s + 2 < nst) fill(s + 2, (s + 2) % 3);

        uint32_t st = sbase + (uint32_t)(s % 3) * STAGE_B;
#pragma unroll
        for (int kk = 0; kk < 2; kk++) {
            uint32_t ah[2][4], al[2][4], bh[4][2], bl[4][2];
#pragma unroll
            for (int ms = 0; ms < 2; ms++) {
                int mtb = (wm >> 3) + ms * 2;
                uint32_t ad = st + (uint32_t)((mtb + (g8 & 1)) * 4 + 2*kk + (g8 >> 1)) * 128 + r8 * 16;
                ldsm4(ah[ms], ad);
                ldsm4(al[ms], ad + 4096);
            }
#pragma unroll
            for (int np = 0; np < 2; np++) {
                int ntb = (wn >> 3) + np * 2;
                uint32_t wd = st + 8192 + (uint32_t)((ntb + (g8 >> 1)) * 4 + 2*kk + (g8 & 1)) * 128 + r8 * 16;
                uint32_t tmp[4];
                ldsm4(tmp, wd);
                bh[2*np][0] = tmp[0]; bh[2*np][1] = tmp[1];
                bh[2*np+1][0] = tmp[2]; bh[2*np+1][1] = tmp[3];
                if (NSP == 3) {
                    ldsm4(tmp, wd + 8192);
                    bl[2*np][0] = tmp[0]; bl[2*np][1] = tmp[1];
                    bl[2*np+1][0] = tmp[2]; bl[2*np+1][1] = tmp[3];
                }
            }
#pragma unroll
            for (int ms = 0; ms < 2; ms++)
#pragma unroll
                for (int ns = 0; ns < 4; ns++) {
                    mma_bf16(acc[ms][ns], ah[ms], bh[ns]);
                    mma_bf16(acc[ms][ns], al[ms], bh[ns]);
                    if (NSP == 3) mma_bf16(acc[ms][ns], ah[ms], bl[ns]);
                }
        }
    }

    // ---- epilogue ----
    auto wpair_h0 = [&](int row, int col, float x, float y) {
        uint32_t hi, lo;
        cvt2(x, y, hi, lo);
        size_t oh = ioff32(row, col, HH);
        ((uint32_t*)g_himg)[oh]            = hi;
        ((uint32_t*)g_himg)[(PE_H>>1)+oh]  = lo;
        size_t og = ioff32(row, col + KG, KGX);
        ((uint32_t*)g_gint)[og]             = hi;
        ((uint32_t*)g_gint)[(PE_GIN>>1)+og] = lo;
    };
    auto epi1 = [&](int m, int n, float v) {
        if (n >= N) return;
        if (MODE == M_PLAIN) {
            C[(size_t)m * N + n] = v;
        } else if (MODE == M_PLAIN16) {
            ((__nv_bfloat16*)C)[(size_t)m * N + n] = __float2bfloat16(v);
        } else if (MODE == M_BIG) {
            if (n < AA)       C[(size_t)m * AA + n] = v;
            else if (n < KG)  out2[(size_t)m * ENC + (n - AA)] = sigf(v);
            else {
                int col = n - KG;
                if (col < VV && g_predlen[m] > t - 1)
                    out3[((size_t)m * TT + (t - 1)) * VV + col] = v;
            }
        } else if (MODE == M_LOGITS) {
            if (g_predlen[m] > t) C[((size_t)m * TT + t) * VV + n] = v;
        }
    };

#pragma unroll
    for (int ms = 0; ms < 2; ms++)
#pragma unroll
        for (int ns = 0; ns < 4; ns++) {
            int row = m0 + wm + ms*16 + r;
            int col = n0 + wn + ns*8 + 2*c;
            float4 d = acc[ms][ns];
            float bx = 0.f, by = 0.f;
            if (bias && col < N)     bx = bias[col];
            if (bias && col + 1 < N) by = bias[col + 1];
            float vx = d.x + bx, vy = d.y + by;
            float vz = d.z + bx, vw = d.w + by;
            if (MODE == M_H0) {
                wpair_h0(row,     col, vx, vy);
                wpair_h0(row + 8, col, vz, vw);
            } else {
                epi1(row,     col,     vx);
                epi1(row,     col + 1, vy);
                epi1(row + 8, col,     vz);
                epi1(row + 8, col + 1, vw);
            }
        }
}

// ---------------- attention: x_t gather + scores + softmax -> alpha (512 thr) ---
__global__ void attn_kernel(const float* __restrict__ emb,
                            const float* __restrict__ fw,
                            const float* __restrict__ fb, int t)
{
    int b = blockIdx.x;
    if (g_predlen[b] <= t) return;
    __shared__ float s_fw[AA], s_hid[AA], s_a[200], s_r[16];
    int tid = threadIdx.x;

    if (tid < 64) {
        int cap = g_caps[b*SS + t];
        const float4* e = (const float4*)(emb + (size_t)cap * EE) + tid*2;
        float4 v0 = e[0], v1 = e[1];
        uint32_t h0,l0,h1,l1,h2,l2,h3,l3;
        cvt2(v0.x, v0.y, h0, l0); cvt2(v0.z, v0.w, h1, l1);
        cvt2(v1.x, v1.y, h2, l2); cvt2(v1.z, v1.w, h3, l3);
        size_t off = ioff32(b, tid*8, KGX);
        *(uint4*)((uint32_t*)g_gint + off)              = make_uint4(h0,h1,h2,h3);
        *(uint4*)((uint32_t*)g_gint + (PE_GIN>>1)+off)  = make_uint4(l0,l1,l2,l3);
    }
    s_fw[tid]  = fw[tid];
    s_hid[tid] = g_hidatt[b*AA + tid];
    __syncthreads();

    int warp = tid >> 5, lane = tid & 31;
    int ord = g_order[b];
    const __nv_bfloat162* base16 =
        (const __nv_bfloat162*)(g_encatt16 + (size_t)ord * PP * AA);
    for (int p = warp; p < PP; p += 16) {
        const __nv_bfloat162* row = base16 + (size_t)p * (AA/2);
        float acc = 0.f;
#pragma unroll
        for (int a2 = lane; a2 < AA/2; a2 += 32) {
            float2 f = __bfloat1622float2(row[a2]);
            int a = 2*a2;
            acc += fmaxf(f.x + s_hid[a],     0.f) * s_fw[a]
                 + fmaxf(f.y + s_hid[a + 1], 0.f) * s_fw[a + 1];
        }
        for (int o = 16; o; o >>= 1) acc += __shfl_xor_sync(0xFFFFFFFFu, acc, o);
        if (!lane) s_a[p] = acc;
    }
    __syncthreads();

    float v = (tid < PP) ? (s_a[tid] + fb[0]) : -1e30f;
    float m = v;
    for (int o = 16; o; o >>= 1) m = fmaxf(m, __shfl_xor_sync(0xFFFFFFFFu, m, o));
    if (!lane) s_r[warp] = m;
    __syncthreads();
    float bm = s_r[0];
    for (int i = 1; i < 16; i++) bm = fmaxf(bm, s_r[i]);
    __syncthreads();
    float ex = (tid < PP) ? expf(v - bm) : 0.f;
    float sm = ex;
    for (int o = 16; o; o >>= 1) sm += __shfl_xor_sync(0xFFFFFFFFu, sm, o);
    if (!lane) s_r[warp] = sm;
    __syncthreads();
    float bs = 0.f;
    for (int i = 0; i < 16; i++) bs += s_r[i];
    if (tid < PP) g_alpha[b*PP + tid] = ex / bs;
}

// ---------------- gated context: high-parallelism stream ----------------
__global__ void ctx_kernel(int t)
{
    int b = blockIdx.y;
    if (g_predlen[b] <= t) return;
    __shared__ float s_a[PP];
    int tid = threadIdx.x;
    if (tid < PP) s_a[tid] = g_alpha[b*PP + tid];
    __syncthreads();

    int ord = g_order[b];
    int ch = blockIdx.x * 512 + tid * 2;
    const __nv_bfloat162* imgb =
        (const __nv_bfloat162*)(g_img16 + (size_t)ord * PP * ENC) + (ch >> 1);
    float a0 = 0.f, a1 = 0.f;
#pragma unroll 7
    for (int p = 0; p < PP; p++) {
        float2 f = __bfloat1622float2(imgb[(size_t)p * (ENC/2)]);
        float al = s_a[p];
        a0 = fmaf(al, f.x, a0);
        a1 = fmaf(al, f.y, a1);
    }
    const float* gsb = g_gs + (size_t)b * ENC + ch;
    uint32_t hi, lo;
    cvt2(a0 * gsb[0], a1 * gsb[1], hi, lo);
    size_t off = ioff32(b, EE + ch, KGX);
    ((uint32_t*)g_gint)[off]             = hi;
    ((uint32_t*)g_gint)[(PE_GIN>>1)+off] = lo;
}

// ---------------- LSTM cell ----------------
__global__ void cell_kernel(int t)
{
    int b = blockIdx.x;
    if (g_predlen[b] <= t) return;
    int k = threadIdx.x * 2;
    size_t o = (size_t)b * 4*HH;
    float hv[2];
#pragma unroll
    for (int e = 0; e < 2; e++) {
        int j = k + e;
        float si = g_bias_gates[j],        sf = g_bias_gates[j + HH];
        float sg = g_bias_gates[j + 2*HH], so = g_bias_gates[j + 3*HH];
#pragma unroll
        for (int z = 0; z < NSPLITK; z++) {
            si += g_gpart[z][o + j];
            sf += g_gpart[z][o + j + HH];
            sg += g_gpart[z][o + j + 2*HH];
            so += g_gpart[z][o + j + 3*HH];
        }
        float ig = sigf(si), fg = sigf(sf), gg = tanhf(sg), og = sigf(so);
        float cc = fg * g_c[b*HH + j] + ig * gg;
        g_c[b*HH + j] = cc;
        hv[e] = og * tanhf(cc);
    }
    uint32_t hi, lo;
    cvt2(hv[0], hv[1], hi, lo);
    size_t oh = ioff32(b, k, HH);
    ((uint32_t*)g_himg)[oh]           = hi;
    ((uint32_t*)g_himg)[(PE_H>>1)+oh] = lo;
    size_t og2 = ioff32(b, k + KG, KGX);
    ((uint32_t*)g_gint)[og2]             = hi;
    ((uint32_t*)g_gint)[(PE_GIN>>1)+og2] = lo;
}

// ---------------- launch ----------------
extern "C" void kernel_launch(void* const* d_in, const int* in_sizes, int n_in,
                              void* d_out, int out_size)
{
    const float* img   = (const float*)d_in[0];
    const int*   caps  = (const int*)d_in[1];
    const int*   clen  = (const int*)d_in[2];
    const float* emb   = (const float*)d_in[3];
    const float* W_ih  = (const float*)d_in[4];
    const float* W_hh  = (const float*)d_in[5];
    const float* b_ih  = (const float*)d_in[6];
    const float* b_hh  = (const float*)d_in[7];
    const float* ec_w  = (const float*)d_in[8];
    const float* ec_b  = (const float*)d_in[9];
    const float* eh_w  = (const float*)d_in[10];
    const float* eh_b  = (const float*)d_in[11];
    const float* sag_w = (const float*)d_in[12];
    const float* sag_b = (const float*)d_in[13];
    const float* ae_w  = (const float*)d_in[14];
    const float* ae_b  = (const float*)d_in[15];
    const float* ah_w  = (const float*)d_in[16];
    const float* ah_b  = (const float*)d_in[17];
    const float* af_w  = (const float*)d_in[18];
    const float* af_b  = (const float*)d_in[19];
    const float* fc_w  = (const float*)d_in[20];
    const float* fc_b  = (const float*)d_in[21];
    float* out = (float*)d_out;

    float *p_c, *p_hid, *p_gs, *p_gpart, *p_bigb;
    uint16_t *p_Wgt, *p_bigw, *p_aet, *p_eht, *p_ect, *p_imgt, *p_meani, *p_himg, *p_gint;
    __nv_bfloat16 *p_ea16;
    cudaGetSymbolAddress((void**)&p_c,     g_c);
    cudaGetSymbolAddress((void**)&p_hid,   g_hidatt);
    cudaGetSymbolAddress((void**)&p_gs,    g_gs);
    cudaGetSymbolAddress((void**)&p_gpart, g_gpart);
    cudaGetSymbolAddress((void**)&p_bigb,  g_bias_big);
    cudaGetSymbolAddress((void**)&p_Wgt,   g_Wgt);
    cudaGetSymbolAddress((void**)&p_bigw,  g_bigw);
    cudaGetSymbolAddress((void**)&p_aet,   g_aet);
    cudaGetSymbolAddress((void**)&p_eht,   g_eht);
    cudaGetSymbolAddress((void**)&p_ect,   g_ect);
    cudaGetSymbolAddress((void**)&p_imgt,  g_imgt);
    cudaGetSymbolAddress((void**)&p_meani, g_meani);
    cudaGetSymbolAddress((void**)&p_himg,  g_himg);
    cudaGetSymbolAddress((void**)&p_gint,  g_gint);
    cudaGetSymbolAddress((void**)&p_ea16,  g_encatt16);

    cudaFuncSetAttribute(kmma<2, M_PLAIN16, false>, cudaFuncAttributeMaxDynamicSharedMemorySize, SMEM_DYN);
    cudaFuncSetAttribute(kmma<3, M_H0,      false>, cudaFuncAttributeMaxDynamicSharedMemorySize, SMEM_DYN);
    cudaFuncSetAttribute(kmma<3, M_PLAIN,   false>, cudaFuncAttributeMaxDynamicSharedMemorySize, SMEM_DYN);
    cudaFuncSetAttribute(kmma<3, M_BIG,     false>, cudaFuncAttributeMaxDynamicSharedMemorySize, SMEM_DYN);
    cudaFuncSetAttribute(kmma<3, M_PLAIN,   true >, cudaFuncAttributeMaxDynamicSharedMemorySize, SMEM_DYN);
    cudaFuncSetAttribute(kmma<3, M_LOGITS,  true >, cudaFuncAttributeMaxDynamicSharedMemorySize, SMEM_DYN);

    cudaMemsetAsync(d_out, 0, (size_t)out_size * sizeof(float));
    setup_kernel<<<1, 256>>>(caps, clen, b_ih, b_hh, ah_b, sag_b, fc_b, out);
    build_all<<<GRID_BUILD, 256>>>(W_ih, W_hh, ah_w, sag_w, fc_w, ae_w, eh_w, ec_w, img);
    mean_kernel<<<dim3(ENC/512, BB), 256>>>(img);

    // enc_att precompute (x2, bf16 out): M=50176, N=512, K=2048
    kmma<2, M_PLAIN16, false><<<dim3(AA/128, (BB*PP)/64), 256, SMEM_DYN>>>(
        p_imgt, ENC, PE_IMG, p_aet, ENC, PE_AE, ae_b, (float*)p_ea16,
        BB*PP, AA, ENC, 0, nullptr, nullptr);

    // h0 (-> h image + gatesin image), c0 (-> flat c)
    kmma<3, M_H0, false><<<dim3(HH/128, BB/64), 256, SMEM_DYN>>>(
        p_meani, ENC, PE_MEAN, p_eht, ENC, PE_EH, eh_b, nullptr,
        BB, HH, ENC, 0, nullptr, nullptr);
    kmma<3, M_PLAIN, false><<<dim3(HH/128, BB/64), 256, SMEM_DYN>>>(
        p_meani, ENC, PE_MEAN, p_ect, ENC, PE_EH, ec_b, p_c,
        BB, HH, ENC, 0, nullptr, nullptr);

    for (int t = 0; t < TT; t++) {
        // merged: hid_att(t) + gs(t) + logits(t-1); M=256 N=12672 K=512
        kmma<3, M_BIG, false><<<dim3(NBIG/128, BB/64), 256, SMEM_DYN>>>(
            p_himg, HH, PE_H, p_bigw, HH, PE_BIG, p_bigb, p_hid,
            BB, NBIG, HH, t, p_gs, out + OUT_PRED_OFF);
        // attention scores + softmax (+ x_t gather)
        attn_kernel<<<BB, 512>>>(emb, af_w, af_b, t);
        // gated context
        ctx_kernel<<<dim3(ENC/512, BB), 256>>>(t);
        // gates split-K=4 (x3): M=256 N=2048 K=3072 (Klen=768)
        kmma<3, M_PLAIN, true><<<dim3((4*HH)/128, BB/64, NSPLITK), 256, SMEM_DYN>>>(
            p_gint, KGX, PE_GIN, p_Wgt, KGX, PE_WG, nullptr, p_gpart,
            BB, 4*HH, KGX/NSPLITK, t, nullptr, nullptr);
        cell_kernel<<<BB, 256>>>(t);
    }
    // tail: logits(TT-1) from final h (weight rows KG.. of big image)
    kmma<3, M_LOGITS, true><<<dim3(VVP/128, BB/64), 256, SMEM_DYN>>>(
        p_himg, HH, PE_H, p_bigw + (size_t)KG*HH, HH, PE_BIG, fc_b,
        out + OUT_PRED_OFF, BB, VV, HH, TT-1, nullptr, nullptr);
}

// round 15
// speedup vs baseline: 1.4118x; 1.4118x over previous
#include <cuda_runtime.h>
#include <cuda_bf16.h>
#include <cstdint>

#define BB   256
#define PP   196
#define ENC  2048
#define VV   10000
#define VVP  10112
#define EE   512
#define HH   512
#define AA   512
#define SS   54
#define TT   53
#define KG   2560
#define KGX  3072
#define OUT_PRED_OFF (BB + BB*SS)
#define NSPLITK 4
#define STAGE_B 24576
#define SMEM_DYN (3*STAGE_B)
#define MALL (TT*BB)             // 13568 rows of h_all

__device__ int   g_order[BB];
__device__ int   g_predlen[BB];
__device__ int   g_caps[BB*SS];
__device__ float g_bias_gates[4*HH];
__device__ float g_bias_fused[KG];
__device__ float g_c[BB*HH];
__device__ float g_hidatt[BB*AA];
__device__ float g_gs[BB*ENC];
__device__ float g_alpha[BB*PP];
__device__ float g_gpart[NSPLITK][BB*4*HH];

// tiled bf16 hi/lo images (hi plane then lo plane), 8x8 tiles of 128B
#define PE_WG   ((size_t)(4*HH)*KGX)
#define PE_WHG  ((size_t)KG*HH)
#define PE_FC   ((size_t)VVP*HH)
#define PE_AE   ((size_t)AA*ENC)
#define PE_EH   ((size_t)HH*ENC)
#define PE_IMG  ((size_t)BB*PP*ENC)
#define PE_MEAN ((size_t)BB*ENC)
#define PE_H    ((size_t)BB*HH)
#define PE_GIN  ((size_t)BB*KGX)
#define PE_HALL ((size_t)MALL*HH)

__device__ __align__(128) uint16_t g_Wgt  [2*PE_WG];
__device__ __align__(128) uint16_t g_Whgt [2*PE_WHG];   // [ah_w ; sag_w]
__device__ __align__(128) uint16_t g_fct  [2*PE_FC];
__device__ __align__(128) uint16_t g_aet  [2*PE_AE];
__device__ __align__(128) uint16_t g_eht  [2*PE_EH];
__device__ __align__(128) uint16_t g_ect  [2*PE_EH];
__device__ __align__(128) uint16_t g_imgt [2*PE_IMG];
__device__ __align__(128) uint16_t g_meani[2*PE_MEAN];
__device__ __align__(128) uint16_t g_himg [2*PE_H];
__device__ __align__(128) uint16_t g_gint [2*PE_GIN];
__device__ __align__(128) uint16_t g_hall [2*PE_HALL];  // h(t) for all steps
__device__ __align__(16)  __nv_bfloat16 g_img16[PE_IMG];
__device__ __align__(16)  __nv_bfloat16 g_encatt16[(size_t)BB*PP*AA];

__device__ __forceinline__ float sigf(float x) { return 1.f / (1.f + expf(-x)); }

__device__ __forceinline__ void cvt2(float x, float y, uint32_t& hi, uint32_t& lo) {
    __nv_bfloat162 h = __floats2bfloat162_rn(x, y);
    float rx = x - __bfloat162float(h.x);
    float ry = y - __bfloat162float(h.y);
    __nv_bfloat162 l = __floats2bfloat162_rn(rx, ry);
    hi = *(uint32_t*)&h;
    lo = *(uint32_t*)&l;
}

__device__ __forceinline__ size_t ioff32(int n, int k, int Kd) {
    return ((size_t)(n >> 3) * (Kd >> 3) + (k >> 3)) * 32 + (n & 7) * 4 + ((k & 7) >> 1);
}

__device__ __forceinline__ uint32_t smem_u32(const void* p) {
    uint32_t a;
    asm("{ .reg .u64 t; cvta.to.shared.u64 t, %1; cvt.u32.u64 %0, t; }" : "=r"(a) : "l"(p));
    return a;
}

__device__ __forceinline__ void mma_bf16(float4& d, const uint32_t a[4], const uint32_t b[2]) {
    asm volatile(
        "mma.sync.aligned.m16n8k16.row.col.f32.bf16.bf16.f32 "
        "{%0,%1,%2,%3}, {%4,%5,%6,%7}, {%8,%9}, {%0,%1,%2,%3};\n"
        : "+f"(d.x), "+f"(d.y), "+f"(d.z), "+f"(d.w)
        : "r"(a[0]), "r"(a[1]), "r"(a[2]), "r"(a[3]), "r"(b[0]), "r"(b[1]));
}

__device__ __forceinline__ void ldsm4(uint32_t r[4], uint32_t addr) {
    asm volatile("ldmatrix.sync.aligned.m8n8.x4.shared.b16 {%0,%1,%2,%3}, [%4];"
        : "=r"(r[0]), "=r"(r[1]), "=r"(r[2]), "=r"(r[3]) : "r"(addr));
}

// ---------------- setup ----------------
__global__ void setup_kernel(const int* __restrict__ caps32,
                             const int* __restrict__ lens32,
                             const float* __restrict__ b_ih,
                             const float* __restrict__ b_hh,
                             const float* __restrict__ ah_b,
                             const float* __restrict__ sag_b,
                             float* __restrict__ out)
{
    __shared__ int s_order[BB];
    __shared__ int s_is64;
    int tid = threadIdx.x;
    if (tid == 0) {
        int is64 = (lens32[1] == 0 && lens32[3] == 0 && lens32[5] == 0) ? 1 : 0;
        s_is64 = is64;
        int cnt[64];
        for (int i = 0; i < 64; i++) cnt[i] = 0;
        for (int i = 0; i < BB; i++) {
            int l = is64 ? lens32[2*i] : lens32[i];
            cnt[max(0, min(63, l))]++;
        }
        int start[64]; int run = 0;
        for (int l = 63; l >= 0; l--) { start[l] = run; run += cnt[l]; }
        for (int i = 0; i < BB; i++) {
            int l = is64 ? lens32[2*i] : lens32[i];
            s_order[start[max(0, min(63, l))]++] = i;
        }
    }
    __syncthreads();
    int is64 = s_is64;
    int b = tid;
    int ord = s_order[b];
    g_order[b] = ord;
    int len = is64 ? lens32[2*ord] : lens32[ord];
    len = max(1, min(SS, len));
    g_predlen[b] = len - 1;
    out[b] = (float)(len - 1);
    for (int s = 0; s < SS; s++) {
        size_t idx = (size_t)ord * SS + s;
        int cap = is64 ? caps32[2*idx] : caps32[idx];
        out[BB + b*SS + s] = (float)cap;
        g_caps[b*SS + s] = max(0, min(VV - 1, cap));
    }
    for (int j = tid; j < 4*HH; j += BB) g_bias_gates[j] = b_ih[j] + b_hh[j];
    for (int j = tid; j < KG; j += BB)
        g_bias_fused[j] = (j < AA) ? ah_b[j] : sag_b[j - AA];
}

// ---------------- single build kernel: all weight + img images ----------------
#define GRID_BUILD 68480
__global__ void build_all(const float* __restrict__ W_ih, const float* __restrict__ W_hh,
                          const float* __restrict__ ah_w, const float* __restrict__ sag_w,
                          const float* __restrict__ fc_w, const float* __restrict__ ae_w,
                          const float* __restrict__ eh_w, const float* __restrict__ ec_w,
                          const float* __restrict__ img)
{
    int bid = blockIdx.x;
    const float* s = nullptr;
    uint16_t* dimg; size_t pe; int n, Ks, koff, Kd; bool flat = false;

    if (bid < 2048)      { s = W_ih + (size_t)bid*KG;  dimg = g_Wgt;  pe = PE_WG;  n = bid;    Ks = KG;  koff = 0;  Kd = KGX; }
    else if (bid < 4096) { int i = bid-2048;  s = W_hh + (size_t)i*HH;  dimg = g_Wgt;  pe = PE_WG;  n = i;       Ks = HH;  koff = KG; Kd = KGX; }
    else if (bid < 4608) { int i = bid-4096;  s = ah_w + (size_t)i*HH;  dimg = g_Whgt; pe = PE_WHG; n = i;       Ks = HH;  koff = 0;  Kd = HH;  }
    else if (bid < 6656) { int i = bid-4608;  s = sag_w + (size_t)i*HH; dimg = g_Whgt; pe = PE_WHG; n = AA+i;    Ks = HH;  koff = 0;  Kd = HH;  }
    else if (bid < 16656){ int i = bid-6656;  s = fc_w + (size_t)i*HH;  dimg = g_fct;  pe = PE_FC;  n = i;       Ks = HH;  koff = 0;  Kd = HH;  }
    else if (bid < 16768){ int i = bid-16656; s = nullptr;              dimg = g_fct;  pe = PE_FC;  n = VV+i;    Ks = HH;  koff = 0;  Kd = HH;  }
    else if (bid < 17280){ int i = bid-16768; s = ae_w + (size_t)i*ENC; dimg = g_aet;  pe = PE_AE;  n = i;       Ks = ENC; koff = 0;  Kd = ENC; }
    else if (bid < 17792){ int i = bid-17280; s = eh_w + (size_t)i*ENC; dimg = g_eht;  pe = PE_EH;  n = i;       Ks = ENC; koff = 0;  Kd = ENC; }
    else if (bid < 18304){ int i = bid-17792; s = ec_w + (size_t)i*ENC; dimg = g_ect;  pe = PE_EH;  n = i;       Ks = ENC; koff = 0;  Kd = ENC; }
    else                 { int i = bid-18304; s = img + (size_t)i*ENC;  dimg = g_imgt; pe = PE_IMG; n = i;       Ks = ENC; koff = 0;  Kd = ENC; flat = true; }

    uint32_t* d32 = (uint32_t*)dimg;
    size_t p32 = pe >> 1;
    for (int p = threadIdx.x; p < Ks/2; p += 256) {
        int k = 2*p;
        float v0 = 0.f, v1 = 0.f;
        if (s) { float2 vv = *(const float2*)(s + k); v0 = vv.x; v1 = vv.y; }
        uint32_t hi, lo;
        cvt2(v0, v1, hi, lo);
        size_t off = ioff32(n, koff + k, Kd);
        d32[off]       = hi;
        d32[p32 + off] = lo;
        if (flat) ((uint32_t*)g_img16)[((size_t)n*ENC + k) >> 1] = hi;
    }
}

// ---------------- mean over pixels -> tiled mean image ----------------
__global__ void mean_kernel(const float* __restrict__ img)
{
    int b  = blockIdx.y;
    int ch = (blockIdx.x * 256 + threadIdx.x) * 2;
    int ord = g_order[b];
    const float2* base = (const float2*)(img + (size_t)ord * PP * ENC) + (ch >> 1);
    float a0 = 0.f, a1 = 0.f;
#pragma unroll 4
    for (int p = 0; p < PP; p++) { float2 v = base[(size_t)p * (ENC/2)]; a0 += v.x; a1 += v.y; }
    a0 *= (1.0f / (float)PP);
    a1 *= (1.0f / (float)PP);
    uint32_t hi, lo;
    cvt2(a0, a1, hi, lo);
    size_t off = ioff32(b, ch, ENC);
    ((uint32_t*)g_meani)[off]             = hi;
    ((uint32_t*)g_meani)[(PE_MEAN>>1)+off]= lo;
}

// ================= bf16 x2/x3 HMMA GEMM: all-cp.async fills, 3-stage ==========
#define M_PLAIN   0
#define M_FUSEDH  1
#define M_LOGB    2
#define M_PLAIN16 3
#define M_H0      4

template<int NSP, int MODE, bool MASKED>
__global__ void __launch_bounds__(256)
kmma(const uint16_t* __restrict__ At, int Ka, size_t pA,
     const uint16_t* __restrict__ Wt, int Kw, size_t pW,
     const float* __restrict__ bias, float* __restrict__ C,
     int M, int N, int Klen, int t)
{
    extern __shared__ __align__(16) char smd[];
    const int m0 = blockIdx.y * 64;
    const int n0 = blockIdx.x * 128;
    if (MASKED && g_predlen[m0] <= t) return;
    if (MODE == M_LOGB) {
        // batched logits: row m -> (t = m>>8, b = m&255); skip inactive block
        if (g_predlen[m0 & 255] <= (m0 >> 8)) return;
    }
    const int kbase = blockIdx.z * Klen;
    if (gridDim.z > 1) C += (size_t)blockIdx.z * M * N;

    const int tid  = threadIdx.x;
    const int lane = tid & 31;
    const int w    = tid >> 5;
    const int wm   = (w & 1) * 32;
    const int wn   = (w >> 1) * 32;
    const int r    = lane >> 2;
    const int c    = lane & 3;
    const int g8   = lane >> 3;
    const int r8   = lane & 7;
    const uint32_t sbase = smem_u32(smd);

    const int a_mt = tid >> 5, a_kt = (tid >> 3) & 3, a_rw = tid & 7;

    float4 acc[2][4];
#pragma unroll
    for (int i = 0; i < 2; i++)
#pragma unroll
        for (int j = 0; j < 4; j++) acc[i][j] = make_float4(0.f, 0.f, 0.f, 0.f);

    auto fill = [&](int s, int buf) {
        int k0 = kbase + s * 32;
        uint32_t sreg = sbase + (uint32_t)buf * STAGE_B;
        {
            size_t tile = (size_t)((m0 >> 3) + a_mt) * (Ka >> 3) + ((k0 >> 3) + a_kt);
            uint32_t so = sreg + (uint32_t)((a_mt * 4 + a_kt) * 128 + a_rw * 16);
            const char* g = (const char*)At + tile * 128 + a_rw * 16;
            asm volatile("cp.async.cg.shared.global [%0], [%1], 16;" :: "r"(so), "l"(g));
            asm volatile("cp.async.cg.shared.global [%0], [%1], 16;"
                         :: "r"(so + 4096), "l"(g + pA * 2));
        }
#pragma unroll
        for (int i = 0; i < (NSP == 3 ? 4 : 2); i++) {
            int plane = i >> 1, half = i & 1;
            int uu = tid + half * 256;
            int nt = uu >> 5, kt = (uu >> 3) & 3, rw = uu & 7;
            size_t tile = (size_t)((n0 >> 3) + nt) * (Kw >> 3) + ((k0 >> 3) + kt);
            const char* g = (const char*)Wt + (size_t)plane * pW * 2 + tile * 128 + rw * 16;
            uint32_t so = sreg + 8192 + (uint32_t)(plane * 8192 + (nt * 4 + kt) * 128 + rw * 16);
            asm volatile("cp.async.cg.shared.global [%0], [%1], 16;" :: "r"(so), "l"(g));
        }
        asm volatile("cp.async.commit_group;" ::: "memory");
    };

    const int nst = Klen / 32;
    fill(0, 0);
    fill(1, 1);
    for (int s = 0; s < nst; s++) {
        if (s + 1 < nst) asm volatile("cp.async.wait_group 1;" ::: "memory");
        else             asm volatile("cp.async.wait_group 0;" ::: "memory");
        __syncthreads();
        if (s + 2 < nst) fill(s + 2, (s + 2) % 3);

        uint32_t st = sbase + (uint32_t)(s % 3) * STAGE_B;
#pragma unroll
        for (int kk = 0; kk < 2; kk++) {
            uint32_t ah[2][4], al[2][4], bh[4][2], bl[4][2];
#pragma unroll
            for (int ms = 0; ms < 2; ms++) {
                int mtb = (wm >> 3) + ms * 2;
                uint32_t ad = st + (uint32_t)((mtb + (g8 & 1)) * 4 + 2*kk + (g8 >> 1)) * 128 + r8 * 16;
                ldsm4(ah[ms], ad);
                ldsm4(al[ms], ad + 4096);
            }
#pragma unroll
            for (int np = 0; np < 2; np++) {
                int ntb = (wn >> 3) + np * 2;
                uint32_t wd = st + 8192 + (uint32_t)((ntb + (g8 >> 1)) * 4 + 2*kk + (g8 & 1)) * 128 + r8 * 16;
                uint32_t tmp[4];
                ldsm4(tmp, wd);
                bh[2*np][0] = tmp[0]; bh[2*np][1] = tmp[1];
                bh[2*np+1][0] = tmp[2]; bh[2*np+1][1] = tmp[3];
                if (NSP == 3) {
                    ldsm4(tmp, wd + 8192);
                    bl[2*np][0] = tmp[0]; bl[2*np][1] = tmp[1];
                    bl[2*np+1][0] = tmp[2]; bl[2*np+1][1] = tmp[3];
                }
            }
#pragma unroll
            for (int ms = 0; ms < 2; ms++)
#pragma unroll
                for (int ns = 0; ns < 4; ns++) {
                    mma_bf16(acc[ms][ns], ah[ms], bh[ns]);
                    mma_bf16(acc[ms][ns], al[ms], bh[ns]);
                    if (NSP == 3) mma_bf16(acc[ms][ns], ah[ms], bl[ns]);
                }
        }
    }

    // ---- epilogue ----
    auto wpair_h0 = [&](int row, int col, float x, float y) {
        uint32_t hi, lo;
        cvt2(x, y, hi, lo);
        size_t oh = ioff32(row, col, HH);
        ((uint32_t*)g_himg)[oh]            = hi;
        ((uint32_t*)g_himg)[(PE_H>>1)+oh]  = lo;
        size_t og = ioff32(row, col + KG, KGX);
        ((uint32_t*)g_gint)[og]             = hi;
        ((uint32_t*)g_gint)[(PE_GIN>>1)+og] = lo;
    };
    auto epi1 = [&](int m, int n, float v) {
        if (n >= N) return;
        if (MODE == M_PLAIN) {
            C[(size_t)m * N + n] = v;
        } else if (MODE == M_PLAIN16) {
            ((__nv_bfloat16*)C)[(size_t)m * N + n] = __float2bfloat16(v);
        } else if (MODE == M_FUSEDH) {
            if (n < AA) C[(size_t)m * AA + n] = v;
            else        g_gs[(size_t)m * ENC + (n - AA)] = sigf(v);
        } else if (MODE == M_LOGB) {
            int bb = m & 255, tt = m >> 8;
            if (n < VV && g_predlen[bb] > tt)
                C[((size_t)bb * TT + tt) * VV + n] = v;
        }
    };

#pragma unroll
    for (int ms = 0; ms < 2; ms++)
#pragma unroll
        for (int ns = 0; ns < 4; ns++) {
            int row = m0 + wm + ms*16 + r;
            int col = n0 + wn + ns*8 + 2*c;
            float4 d = acc[ms][ns];
            float bx = 0.f, by = 0.f;
            if (bias && col < N)     bx = bias[col];
            if (bias && col + 1 < N) by = bias[col + 1];
            float vx = d.x + bx, vy = d.y + by;
            float vz = d.z + bx, vw = d.w + by;
            if (MODE == M_H0) {
                wpair_h0(row,     col, vx, vy);
                wpair_h0(row + 8, col, vz, vw);
            } else {
                epi1(row,     col,     vx);
                epi1(row,     col + 1, vy);
                epi1(row + 8, col,     vz);
                epi1(row + 8, col + 1, vw);
            }
        }
}

// ---------------- attention: x_t gather + scores + softmax -> alpha (512 thr) ---
__global__ void attn_kernel(const float* __restrict__ emb,
                            const float* __restrict__ fw,
                            const float* __restrict__ fb, int t)
{
    int b = blockIdx.x;
    if (g_predlen[b] <= t) return;
    __shared__ float s_fw[AA], s_hid[AA], s_a[200], s_r[16];
    int tid = threadIdx.x;

    if (tid < 64) {
        int cap = g_caps[b*SS + t];
        const float4* e = (const float4*)(emb + (size_t)cap * EE) + tid*2;
        float4 v0 = e[0], v1 = e[1];
        uint32_t h0,l0,h1,l1,h2,l2,h3,l3;
        cvt2(v0.x, v0.y, h0, l0); cvt2(v0.z, v0.w, h1, l1);
        cvt2(v1.x, v1.y, h2, l2); cvt2(v1.z, v1.w, h3, l3);
        size_t off = ioff32(b, tid*8, KGX);
        *(uint4*)((uint32_t*)g_gint + off)              = make_uint4(h0,h1,h2,h3);
        *(uint4*)((uint32_t*)g_gint + (PE_GIN>>1)+off)  = make_uint4(l0,l1,l2,l3);
    }
    s_fw[tid]  = fw[tid];
    s_hid[tid] = g_hidatt[b*AA + tid];
    __syncthreads();

    int warp = tid >> 5, lane = tid & 31;
    int ord = g_order[b];
    const __nv_bfloat162* base16 =
        (const __nv_bfloat162*)(g_encatt16 + (size_t)ord * PP * AA);
    for (int p = warp; p < PP; p += 16) {
        const __nv_bfloat162* row = base16 + (size_t)p * (AA/2);
        float acc = 0.f;
#pragma unroll
        for (int a2 = lane; a2 < AA/2; a2 += 32) {
            float2 f = __bfloat1622float2(row[a2]);
            int a = 2*a2;
            acc += fmaxf(f.x + s_hid[a],     0.f) * s_fw[a]
                 + fmaxf(f.y + s_hid[a + 1], 0.f) * s_fw[a + 1];
        }
        for (int o = 16; o; o >>= 1) acc += __shfl_xor_sync(0xFFFFFFFFu, acc, o);
        if (!lane) s_a[p] = acc;
    }
    __syncthreads();

    float v = (tid < PP) ? (s_a[tid] + fb[0]) : -1e30f;
    float m = v;
    for (int o = 16; o; o >>= 1) m = fmaxf(m, __shfl_xor_sync(0xFFFFFFFFu, m, o));
    if (!lane) s_r[warp] = m;
    __syncthreads();
    float bm = s_r[0];
    for (int i = 1; i < 16; i++) bm = fmaxf(bm, s_r[i]);
    __syncthreads();
    float ex = (tid < PP) ? expf(v - bm) : 0.f;
    float sm = ex;
    for (int o = 16; o; o >>= 1) sm += __shfl_xor_sync(0xFFFFFFFFu, sm, o);
    if (!lane) s_r[warp] = sm;
    __syncthreads();
    float bs = 0.f;
    for (int i = 0; i < 16; i++) bs += s_r[i];
    if (tid < PP) g_alpha[b*PP + tid] = ex / bs;
}

// ---------------- gated context: high-parallelism stream ----------------
__global__ void ctx_kernel(int t)
{
    int b = blockIdx.y;
    if (g_predlen[b] <= t) return;
    __shared__ float s_a[PP];
    int tid = threadIdx.x;
    if (tid < PP) s_a[tid] = g_alpha[b*PP + tid];
    __syncthreads();

    int ord = g_order[b];
    int ch = blockIdx.x * 512 + tid * 2;
    const __nv_bfloat162* imgb =
        (const __nv_bfloat162*)(g_img16 + (size_t)ord * PP * ENC) + (ch >> 1);
    float a0 = 0.f, a1 = 0.f;
#pragma unroll 7
    for (int p = 0; p < PP; p++) {
        float2 f = __bfloat1622float2(imgb[(size_t)p * (ENC/2)]);
        float al = s_a[p];
        a0 = fmaf(al, f.x, a0);
        a1 = fmaf(al, f.y, a1);
    }
    const float* gsb = g_gs + (size_t)b * ENC + ch;
    uint32_t hi, lo;
    cvt2(a0 * gsb[0], a1 * gsb[1], hi, lo);
    size_t off = ioff32(b, EE + ch, KGX);
    ((uint32_t*)g_gint)[off]             = hi;
    ((uint32_t*)g_gint)[(PE_GIN>>1)+off] = lo;
}

// ---------------- LSTM cell: partial sums + activations -> images + h_all ------
__global__ void cell_kernel(int t)
{
    int b = blockIdx.x;
    if (g_predlen[b] <= t) return;
    int k = threadIdx.x * 2;
    size_t o = (size_t)b * 4*HH;
    float hv[2];
#pragma unroll
    for (int e = 0; e < 2; e++) {
        int j = k + e;
        float si = g_bias_gates[j],        sf = g_bias_gates[j + HH];
        float sg = g_bias_gates[j + 2*HH], so = g_bias_gates[j + 3*HH];
#pragma unroll
        for (int z = 0; z < NSPLITK; z++) {
            si += g_gpart[z][o + j];
            sf += g_gpart[z][o + j + HH];
            sg += g_gpart[z][o + j + 2*HH];
            so += g_gpart[z][o + j + 3*HH];
        }
        float ig = sigf(si), fg = sigf(sf), gg = tanhf(sg), og = sigf(so);
        float cc = fg * g_c[b*HH + j] + ig * gg;
        g_c[b*HH + j] = cc;
        hv[e] = og * tanhf(cc);
    }
    uint32_t hi, lo;
    cvt2(hv[0], hv[1], hi, lo);
    size_t oh = ioff32(b, k, HH);
    ((uint32_t*)g_himg)[oh]           = hi;
    ((uint32_t*)g_himg)[(PE_H>>1)+oh] = lo;
    size_t og2 = ioff32(b, k + KG, KGX);
    ((uint32_t*)g_gint)[og2]             = hi;
    ((uint32_t*)g_gint)[(PE_GIN>>1)+og2] = lo;
    size_t oa = ioff32(t*BB + b, k, HH);
    ((uint32_t*)g_hall)[oa]              = hi;
    ((uint32_t*)g_hall)[(PE_HALL>>1)+oa] = lo;
}

// ---------------- launch ----------------
extern "C" void kernel_launch(void* const* d_in, const int* in_sizes, int n_in,
                              void* d_out, int out_size)
{
    const float* img   = (const float*)d_in[0];
    const int*   caps  = (const int*)d_in[1];
    const int*   clen  = (const int*)d_in[2];
    const float* emb   = (const float*)d_in[3];
    const float* W_ih  = (const float*)d_in[4];
    const float* W_hh  = (const float*)d_in[5];
    const float* b_ih  = (const float*)d_in[6];
    const float* b_hh  = (const float*)d_in[7];
    const float* ec_w  = (const float*)d_in[8];
    const float* ec_b  = (const float*)d_in[9];
    const float* eh_w  = (const float*)d_in[10];
    const float* eh_b  = (const float*)d_in[11];
    const float* sag_w = (const float*)d_in[12];
    const float* sag_b = (const float*)d_in[13];
    const float* ae_w  = (const float*)d_in[14];
    const float* ae_b  = (const float*)d_in[15];
    const float* ah_w  = (const float*)d_in[16];
    const float* ah_b  = (const float*)d_in[17];
    const float* af_w  = (const float*)d_in[18];
    const float* af_b  = (const float*)d_in[19];
    const float* fc_w  = (const float*)d_in[20];
    const float* fc_b  = (const float*)d_in[21];
    float* out = (float*)d_out;

    float *p_c, *p_hid, *p_gpart, *p_bf;
    uint16_t *p_Wgt, *p_Whgt, *p_fct, *p_aet, *p_eht, *p_ect, *p_imgt, *p_meani,
             *p_himg, *p_gint, *p_hall;
    __nv_bfloat16 *p_ea16;
    cudaGetSymbolAddress((void**)&p_c,     g_c);
    cudaGetSymbolAddress((void**)&p_hid,   g_hidatt);
    cudaGetSymbolAddress((void**)&p_gpart, g_gpart);
    cudaGetSymbolAddress((void**)&p_bf,    g_bias_fused);
    cudaGetSymbolAddress((void**)&p_Wgt,   g_Wgt);
    cudaGetSymbolAddress((void**)&p_Whgt,  g_Whgt);
    cudaGetSymbolAddress((void**)&p_fct,   g_fct);
    cudaGetSymbolAddress((void**)&p_aet,   g_aet);
    cudaGetSymbolAddress((void**)&p_eht,   g_eht);
    cudaGetSymbolAddress((void**)&p_ect,   g_ect);
    cudaGetSymbolAddress((void**)&p_imgt,  g_imgt);
    cudaGetSymbolAddress((void**)&p_meani, g_meani);
    cudaGetSymbolAddress((void**)&p_himg,  g_himg);
    cudaGetSymbolAddress((void**)&p_gint,  g_gint);
    cudaGetSymbolAddress((void**)&p_hall,  g_hall);
    cudaGetSymbolAddress((void**)&p_ea16,  g_encatt16);

    cudaFuncSetAttribute(kmma<2, M_PLAIN16, false>, cudaFuncAttributeMaxDynamicSharedMemorySize, SMEM_DYN);
    cudaFuncSetAttribute(kmma<3, M_H0,      false>, cudaFuncAttributeMaxDynamicSharedMemorySize, SMEM_DYN);
    cudaFuncSetAttribute(kmma<3, M_PLAIN,   false>, cudaFuncAttributeMaxDynamicSharedMemorySize, SMEM_DYN);
    cudaFuncSetAttribute(kmma<3, M_PLAIN,   true >, cudaFuncAttributeMaxDynamicSharedMemorySize, SMEM_DYN);
    cudaFuncSetAttribute(kmma<3, M_FUSEDH,  true >, cudaFuncAttributeMaxDynamicSharedMemorySize, SMEM_DYN);
    cudaFuncSetAttribute(kmma<3, M_LOGB,    false>, cudaFuncAttributeMaxDynamicSharedMemorySize, SMEM_DYN);

    cudaMemsetAsync(d_out, 0, (size_t)out_size * sizeof(float));
    setup_kernel<<<1, 256>>>(caps, clen, b_ih, b_hh, ah_b, sag_b, out);
    build_all<<<GRID_BUILD, 256>>>(W_ih, W_hh, ah_w, sag_w, fc_w, ae_w, eh_w, ec_w, img);
    mean_kernel<<<dim3(ENC/512, BB), 256>>>(img);

    // enc_att precompute (x2, bf16 out): M=50176, N=512, K=2048
    kmma<2, M_PLAIN16, false><<<dim3(AA/128, (BB*PP)/64), 256, SMEM_DYN>>>(
        p_imgt, ENC, PE_IMG, p_aet, ENC, PE_AE, ae_b, (float*)p_ea16, BB*PP, AA, ENC, 0);

    // h0 (-> h image + gatesin image), c0 (-> flat c)
    kmma<3, M_H0, false><<<dim3(HH/128, BB/64), 256, SMEM_DYN>>>(
        p_meani, ENC, PE_MEAN, p_eht, ENC, PE_EH, eh_b, nullptr, BB, HH, ENC, 0);
    kmma<3, M_PLAIN, false><<<dim3(HH/128, BB/64), 256, SMEM_DYN>>>(
        p_meani, ENC, PE_MEAN, p_ect, ENC, PE_EH, ec_b, p_c, BB, HH, ENC, 0);

    for (int t = 0; t < TT; t++) {
        // fused hid_att + gs (x3): M=256 N=2560 K=512
        kmma<3, M_FUSEDH, true><<<dim3(KG/128, BB/64), 256, SMEM_DYN>>>(
            p_himg, HH, PE_H, p_Whgt, HH, PE_WHG, p_bf, p_hid, BB, KG, HH, t);
        // attention scores + softmax (+ x_t gather)
        attn_kernel<<<BB, 512>>>(emb, af_w, af_b, t);
        // gated context
        ctx_kernel<<<dim3(ENC/512, BB), 256>>>(t);
        // gates split-K=4 (x3): M=256 N=2048 K=3072 (Klen=768)
        kmma<3, M_PLAIN, true><<<dim3((4*HH)/128, BB/64, NSPLITK), 256, SMEM_DYN>>>(
            p_gint, KGX, PE_GIN, p_Wgt, KGX, PE_WG, nullptr, p_gpart, BB, 4*HH, KGX/NSPLITK, t);
        cell_kernel<<<BB, 256>>>(t);
    }

    // batched logits over all steps: M = TT*BB = 13568, N = 10112, K = 512
    kmma<3, M_LOGB, false><<<dim3(VVP/128, MALL/64), 256, SMEM_DYN>>>(
        p_hall, HH, PE_HALL, p_fct, HH, PE_FC, fc_b, out + OUT_PRED_OFF, MALL, VVP, HH, 0);
}

// round 16
// speedup vs baseline: 1.5234x; 1.0791x over previous
#include <cuda_runtime.h>
#include <cuda_bf16.h>
#include <cstdint>

#define BB   256
#define PP   196
#define ENC  2048
#define VV   10000
#define VVP  10112
#define EE   512
#define HH   512
#define AA   512
#define SS   54
#define TT   53
#define KG   2560
#define KGX  3072
#define OUT_PRED_OFF (BB + BB*SS)
#define NSPLITK 8
#define STAGE_B 24576
#define SMEM_DYN (3*STAGE_B)
#define MALL (TT*BB)

__device__ int   g_order[BB];
__device__ int   g_predlen[BB];
__device__ int   g_caps[BB*SS];
__device__ float g_bias_gates[4*HH];
__device__ float g_bias_fused[KG];
__device__ float g_c[BB*HH];
__device__ float g_alpha[BB*PP];
__device__ float g_gpart[NSPLITK][BB*4*HH];
__device__ float g_fhpart[2][(size_t)BB*KG];     // fusedh split-K partials

#define PE_WG   ((size_t)(4*HH)*KGX)
#define PE_WHG  ((size_t)KG*HH)
#define PE_FC   ((size_t)VVP*HH)
#define PE_AE   ((size_t)AA*ENC)
#define PE_EH   ((size_t)HH*ENC)
#define PE_IMG  ((size_t)BB*PP*ENC)
#define PE_MEAN ((size_t)BB*ENC)
#define PE_H    ((size_t)BB*HH)
#define PE_GIN  ((size_t)BB*KGX)
#define PE_HALL ((size_t)MALL*HH)

__device__ __align__(128) uint16_t g_Wgt  [2*PE_WG];
__device__ __align__(128) uint16_t g_Whgt [2*PE_WHG];
__device__ __align__(128) uint16_t g_fct  [2*PE_FC];
__device__ __align__(128) uint16_t g_aet  [2*PE_AE];
__device__ __align__(128) uint16_t g_eht  [2*PE_EH];
__device__ __align__(128) uint16_t g_ect  [2*PE_EH];
__device__ __align__(128) uint16_t g_imgt [2*PE_IMG];   // lo plane unused/unwritten
__device__ __align__(128) uint16_t g_meani[2*PE_MEAN];
__device__ __align__(128) uint16_t g_himg [2*PE_H];
__device__ __align__(128) uint16_t g_gint [2*PE_GIN];
__device__ __align__(128) uint16_t g_hall [2*PE_HALL];
__device__ __align__(16)  __nv_bfloat16 g_img16[PE_IMG];
__device__ __align__(16)  __nv_bfloat16 g_encatt16[(size_t)BB*PP*AA];

__device__ __forceinline__ float sigf(float x) { return 1.f / (1.f + expf(-x)); }

__device__ __forceinline__ void cvt2(float x, float y, uint32_t& hi, uint32_t& lo) {
    __nv_bfloat162 h = __floats2bfloat162_rn(x, y);
    float rx = x - __bfloat162float(h.x);
    float ry = y - __bfloat162float(h.y);
    __nv_bfloat162 l = __floats2bfloat162_rn(rx, ry);
    hi = *(uint32_t*)&h;
    lo = *(uint32_t*)&l;
}

__device__ __forceinline__ size_t ioff32(int n, int k, int Kd) {
    return ((size_t)(n >> 3) * (Kd >> 3) + (k >> 3)) * 32 + (n & 7) * 4 + ((k & 7) >> 1);
}

__device__ __forceinline__ uint32_t smem_u32(const void* p) {
    uint32_t a;
    asm("{ .reg .u64 t; cvta.to.shared.u64 t, %1; cvt.u32.u64 %0, t; }" : "=r"(a) : "l"(p));
    return a;
}

__device__ __forceinline__ void mma_bf16(float4& d, const uint32_t a[4], const uint32_t b[2]) {
    asm volatile(
        "mma.sync.aligned.m16n8k16.row.col.f32.bf16.bf16.f32 "
        "{%0,%1,%2,%3}, {%4,%5,%6,%7}, {%8,%9}, {%0,%1,%2,%3};\n"
        : "+f"(d.x), "+f"(d.y), "+f"(d.z), "+f"(d.w)
        : "r"(a[0]), "r"(a[1]), "r"(a[2]), "r"(a[3]), "r"(b[0]), "r"(b[1]));
}

__device__ __forceinline__ void ldsm4(uint32_t r[4], uint32_t addr) {
    asm volatile("ldmatrix.sync.aligned.m8n8.x4.shared.b16 {%0,%1,%2,%3}, [%4];"
        : "=r"(r[0]), "=r"(r[1]), "=r"(r[2]), "=r"(r[3]) : "r"(addr));
}

// ---------------- setup ----------------
__global__ void setup_kernel(const int* __restrict__ caps32,
                             const int* __restrict__ lens32,
                             const float* __restrict__ b_ih,
                             const float* __restrict__ b_hh,
                             const float* __restrict__ ah_b,
                             const float* __restrict__ sag_b,
                             float* __restrict__ out)
{
    __shared__ int s_order[BB];
    __shared__ int s_is64;
    int tid = threadIdx.x;
    if (tid == 0) {
        int is64 = (lens32[1] == 0 && lens32[3] == 0 && lens32[5] == 0) ? 1 : 0;
        s_is64 = is64;
        int cnt[64];
        for (int i = 0; i < 64; i++) cnt[i] = 0;
        for (int i = 0; i < BB; i++) {
            int l = is64 ? lens32[2*i] : lens32[i];
            cnt[max(0, min(63, l))]++;
        }
        int start[64]; int run = 0;
        for (int l = 63; l >= 0; l--) { start[l] = run; run += cnt[l]; }
        for (int i = 0; i < BB; i++) {
            int l = is64 ? lens32[2*i] : lens32[i];
            s_order[start[max(0, min(63, l))]++] = i;
        }
    }
    __syncthreads();
    int is64 = s_is64;
    int b = tid;
    int ord = s_order[b];
    g_order[b] = ord;
    int len = is64 ? lens32[2*ord] : lens32[ord];
    len = max(1, min(SS, len));
    g_predlen[b] = len - 1;
    out[b] = (float)(len - 1);
    for (int s = 0; s < SS; s++) {
        size_t idx = (size_t)ord * SS + s;
        int cap = is64 ? caps32[2*idx] : caps32[idx];
        out[BB + b*SS + s] = (float)cap;
        g_caps[b*SS + s] = max(0, min(VV - 1, cap));
    }
    for (int j = tid; j < 4*HH; j += BB) g_bias_gates[j] = b_ih[j] + b_hh[j];
    for (int j = tid; j < KG; j += BB)
        g_bias_fused[j] = (j < AA) ? ah_b[j] : sag_b[j - AA];
}

// ---------------- single build kernel: all weight + img images ----------------
#define GRID_BUILD 68480
__global__ void build_all(const float* __restrict__ W_ih, const float* __restrict__ W_hh,
                          const float* __restrict__ ah_w, const float* __restrict__ sag_w,
                          const float* __restrict__ fc_w, const float* __restrict__ ae_w,
                          const float* __restrict__ eh_w, const float* __restrict__ ec_w,
                          const float* __restrict__ img)
{
    int bid = blockIdx.x;
    const float* s = nullptr;
    uint16_t* dimg; size_t pe; int n, Ks, koff, Kd; bool flat = false;

    if (bid < 2048)      { s = W_ih + (size_t)bid*KG;  dimg = g_Wgt;  pe = PE_WG;  n = bid;    Ks = KG;  koff = 0;  Kd = KGX; }
    else if (bid < 4096) { int i = bid-2048;  s = W_hh + (size_t)i*HH;  dimg = g_Wgt;  pe = PE_WG;  n = i;       Ks = HH;  koff = KG; Kd = KGX; }
    else if (bid < 4608) { int i = bid-4096;  s = ah_w + (size_t)i*HH;  dimg = g_Whgt; pe = PE_WHG; n = i;       Ks = HH;  koff = 0;  Kd = HH;  }
    else if (bid < 6656) { int i = bid-4608;  s = sag_w + (size_t)i*HH; dimg = g_Whgt; pe = PE_WHG; n = AA+i;    Ks = HH;  koff = 0;  Kd = HH;  }
    else if (bid < 16656){ int i = bid-6656;  s = fc_w + (size_t)i*HH;  dimg = g_fct;  pe = PE_FC;  n = i;       Ks = HH;  koff = 0;  Kd = HH;  }
    else if (bid < 16768){ int i = bid-16656; s = nullptr;              dimg = g_fct;  pe = PE_FC;  n = VV+i;    Ks = HH;  koff = 0;  Kd = HH;  }
    else if (bid < 17280){ int i = bid-16768; s = ae_w + (size_t)i*ENC; dimg = g_aet;  pe = PE_AE;  n = i;       Ks = ENC; koff = 0;  Kd = ENC; }
    else if (bid < 17792){ int i = bid-17280; s = eh_w + (size_t)i*ENC; dimg = g_eht;  pe = PE_EH;  n = i;       Ks = ENC; koff = 0;  Kd = ENC; }
    else if (bid < 18304){ int i = bid-17792; s = ec_w + (size_t)i*ENC; dimg = g_ect;  pe = PE_EH;  n = i;       Ks = ENC; koff = 0;  Kd = ENC; }
    else                 { int i = bid-18304; s = img + (size_t)i*ENC;  dimg = g_imgt; pe = PE_IMG; n = i;       Ks = ENC; koff = 0;  Kd = ENC; flat = true; }

    uint32_t* d32 = (uint32_t*)dimg;
    size_t p32 = pe >> 1;
    for (int p = threadIdx.x; p < Ks/2; p += 256) {
        int k = 2*p;
        float v0 = 0.f, v1 = 0.f;
        if (s) { float2 vv = *(const float2*)(s + k); v0 = vv.x; v1 = vv.y; }
        uint32_t hi, lo;
        cvt2(v0, v1, hi, lo);
        size_t off = ioff32(n, koff + k, Kd);
        d32[off] = hi;
        if (!flat) d32[p32 + off] = lo;          // img image: hi plane only
        else ((uint32_t*)g_img16)[((size_t)n*ENC + k) >> 1] = hi;
    }
}

// ---------------- mean over pixels -> tiled mean image ----------------
__global__ void mean_kernel(const float* __restrict__ img)
{
    int b  = blockIdx.y;
    int ch = (blockIdx.x * 256 + threadIdx.x) * 2;
    int ord = g_order[b];
    const float2* base = (const float2*)(img + (size_t)ord * PP * ENC) + (ch >> 1);
    float a0 = 0.f, a1 = 0.f;
#pragma unroll 4
    for (int p = 0; p < PP; p++) { float2 v = base[(size_t)p * (ENC/2)]; a0 += v.x; a1 += v.y; }
    a0 *= (1.0f / (float)PP);
    a1 *= (1.0f / (float)PP);
    uint32_t hi, lo;
    cvt2(a0, a1, hi, lo);
    size_t off = ioff32(b, ch, ENC);
    ((uint32_t*)g_meani)[off]             = hi;
    ((uint32_t*)g_meani)[(PE_MEAN>>1)+off]= lo;
}

// ================= bf16 HMMA GEMM: plane-flagged decomposition ==========
// terms: hi*hi always; lo(A)*hi if ALO; hi*lo(W) if WLO.  x3 = ALO&&WLO.
#define M_PLAIN   0
#define M_LOGB    2
#define M_PLAIN16 3
#define M_H0      4

template<bool ALO, bool WLO, int MODE, bool MASKED>
__global__ void __launch_bounds__(256)
kmma(const uint16_t* __restrict__ At, int Ka, size_t pA,
     const uint16_t* __restrict__ Wt, int Kw, size_t pW,
     const float* __restrict__ bias, float* __restrict__ C,
     int M, int N, int Klen, int t)
{
    extern __shared__ __align__(16) char smd[];
    const int m0 = blockIdx.y * 64;
    const int n0 = blockIdx.x * 128;
    if (MASKED && g_predlen[m0] <= t) return;
    if (MODE == M_LOGB) {
        if (g_predlen[m0 & 255] <= (m0 >> 8)) return;
    }
    const int kbase = blockIdx.z * Klen;
    if (gridDim.z > 1) C += (size_t)blockIdx.z * M * N;

    const int tid  = threadIdx.x;
    const int lane = tid & 31;
    const int w    = tid >> 5;
    const int wm   = (w & 1) * 32;
    const int wn   = (w >> 1) * 32;
    const int r    = lane >> 2;
    const int c    = lane & 3;
    const int g8   = lane >> 3;
    const int r8   = lane & 7;
    const uint32_t sbase = smem_u32(smd);

    const int a_mt = tid >> 5, a_kt = (tid >> 3) & 3, a_rw = tid & 7;

    float4 acc[2][4];
#pragma unroll
    for (int i = 0; i < 2; i++)
#pragma unroll
        for (int j = 0; j < 4; j++) acc[i][j] = make_float4(0.f, 0.f, 0.f, 0.f);

    auto fill = [&](int s, int buf) {
        int k0 = kbase + s * 32;
        uint32_t sreg = sbase + (uint32_t)buf * STAGE_B;
        {
            size_t tile = (size_t)((m0 >> 3) + a_mt) * (Ka >> 3) + ((k0 >> 3) + a_kt);
            uint32_t so = sreg + (uint32_t)((a_mt * 4 + a_kt) * 128 + a_rw * 16);
            const char* g = (const char*)At + tile * 128 + a_rw * 16;
            asm volatile("cp.async.cg.shared.global [%0], [%1], 16;" :: "r"(so), "l"(g));
            if (ALO)
                asm volatile("cp.async.cg.shared.global [%0], [%1], 16;"
                             :: "r"(so + 4096), "l"(g + pA * 2));
        }
#pragma unroll
        for (int i = 0; i < (WLO ? 4 : 2); i++) {
            int plane = i >> 1, half = i & 1;
            int uu = tid + half * 256;
            int nt = uu >> 5, kt = (uu >> 3) & 3, rw = uu & 7;
            size_t tile = (size_t)((n0 >> 3) + nt) * (Kw >> 3) + ((k0 >> 3) + kt);
            const char* g = (const char*)Wt + (size_t)plane * pW * 2 + tile * 128 + rw * 16;
            uint32_t so = sreg + 8192 + (uint32_t)(plane * 8192 + (nt * 4 + kt) * 128 + rw * 16);
            asm volatile("cp.async.cg.shared.global [%0], [%1], 16;" :: "r"(so), "l"(g));
        }
        asm volatile("cp.async.commit_group;" ::: "memory");
    };

    const int nst = Klen / 32;
    fill(0, 0);
    fill(1, 1);
    for (int s = 0; s < nst; s++) {
        if (s + 1 < nst) asm volatile("cp.async.wait_group 1;" ::: "memory");
        else             asm volatile("cp.async.wait_group 0;" ::: "memory");
        __syncthreads();
        if (s + 2 < nst) fill(s + 2, (s + 2) % 3);

        uint32_t st = sbase + (uint32_t)(s % 3) * STAGE_B;
#pragma unroll
        for (int kk = 0; kk < 2; kk++) {
            uint32_t ah[2][4], al[2][4], bh[4][2], bl[4][2];
#pragma unroll
            for (int ms = 0; ms < 2; ms++) {
                int mtb = (wm >> 3) + ms * 2;
                uint32_t ad = st + (uint32_t)((mtb + (g8 & 1)) * 4 + 2*kk + (g8 >> 1)) * 128 + r8 * 16;
                ldsm4(ah[ms], ad);
                if (ALO) ldsm4(al[ms], ad + 4096);
            }
#pragma unroll
            for (int np = 0; np < 2; np++) {
                int ntb = (wn >> 3) + np * 2;
                uint32_t wd = st + 8192 + (uint32_t)((ntb + (g8 >> 1)) * 4 + 2*kk + (g8 & 1)) * 128 + r8 * 16;
                uint32_t tmp[4];
                ldsm4(tmp, wd);
                bh[2*np][0] = tmp[0]; bh[2*np][1] = tmp[1];
                bh[2*np+1][0] = tmp[2]; bh[2*np+1][1] = tmp[3];
                if (WLO) {
                    ldsm4(tmp, wd + 8192);
                    bl[2*np][0] = tmp[0]; bl[2*np][1] = tmp[1];
                    bl[2*np+1][0] = tmp[2]; bl[2*np+1][1] = tmp[3];
                }
            }
#pragma unroll
            for (int ms = 0; ms < 2; ms++)
#pragma unroll
                for (int ns = 0; ns < 4; ns++) {
                    mma_bf16(acc[ms][ns], ah[ms], bh[ns]);
                    if (ALO) mma_bf16(acc[ms][ns], al[ms], bh[ns]);
                    if (WLO) mma_bf16(acc[ms][ns], ah[ms], bl[ns]);
                }
        }
    }

    // ---- epilogue ----
    auto wpair_h0 = [&](int row, int col, float x, float y) {
        uint32_t hi, lo;
        cvt2(x, y, hi, lo);
        size_t oh = ioff32(row, col, HH);
        ((uint32_t*)g_himg)[oh]            = hi;
        ((uint32_t*)g_himg)[(PE_H>>1)+oh]  = lo;
        size_t og = ioff32(row, col + KG, KGX);
        ((uint32_t*)g_gint)[og]             = hi;
        ((uint32_t*)g_gint)[(PE_GIN>>1)+og] = lo;
    };
    auto epi1 = [&](int m, int n, float v) {
        if (n >= N) return;
        if (MODE == M_PLAIN) {
            C[(size_t)m * N + n] = v;
        } else if (MODE == M_PLAIN16) {
            ((__nv_bfloat16*)C)[(size_t)m * N + n] = __float2bfloat16(v);
        } else if (MODE == M_LOGB) {
            int bb = m & 255, tt = m >> 8;
            if (n < VV && g_predlen[bb] > tt)
                C[((size_t)bb * TT + tt) * VV + n] = v;
        }
    };

#pragma unroll
    for (int ms = 0; ms < 2; ms++)
#pragma unroll
        for (int ns = 0; ns < 4; ns++) {
            int row = m0 + wm + ms*16 + r;
            int col = n0 + wn + ns*8 + 2*c;
            float4 d = acc[ms][ns];
            float bx = 0.f, by = 0.f;
            if (bias && col < N)     bx = bias[col];
            if (bias && col + 1 < N) by = bias[col + 1];
            float vx = d.x + bx, vy = d.y + by;
            float vz = d.z + bx, vw = d.w + by;
            if (MODE == M_H0) {
                wpair_h0(row,     col, vx, vy);
                wpair_h0(row + 8, col, vz, vw);
            } else {
                epi1(row,     col,     vx);
                epi1(row,     col + 1, vy);
                epi1(row + 8, col,     vz);
                epi1(row + 8, col + 1, vw);
            }
        }
}

// ---------------- attention: x_t gather + scores + softmax (512 thr) ----------
__global__ void attn_kernel(const float* __restrict__ emb,
                            const float* __restrict__ fw,
                            const float* __restrict__ fb, int t)
{
    int b = blockIdx.x;
    if (g_predlen[b] <= t) return;
    __shared__ float s_fw[AA], s_hid[AA], s_a[200], s_r[16];
    int tid = threadIdx.x;

    if (tid < 64) {
        int cap = g_caps[b*SS + t];
        const float4* e = (const float4*)(emb + (size_t)cap * EE) + tid*2;
        float4 v0 = e[0], v1 = e[1];
        uint32_t h0,l0,h1,l1,h2,l2,h3,l3;
        cvt2(v0.x, v0.y, h0, l0); cvt2(v0.z, v0.w, h1, l1);
        cvt2(v1.x, v1.y, h2, l2); cvt2(v1.z, v1.w, h3, l3);
        size_t off = ioff32(b, tid*8, KGX);
        *(uint4*)((uint32_t*)g_gint + off)              = make_uint4(h0,h1,h2,h3);
        *(uint4*)((uint32_t*)g_gint + (PE_GIN>>1)+off)  = make_uint4(l0,l1,l2,l3);
    }
    s_fw[tid]  = fw[tid];
    // hid_att = sum of fusedh split-K partials + bias
    s_hid[tid] = g_fhpart[0][(size_t)b*KG + tid] + g_fhpart[1][(size_t)b*KG + tid]
               + g_bias_fused[tid];
    __syncthreads();

    int warp = tid >> 5, lane = tid & 31;
    int ord = g_order[b];
    const __nv_bfloat162* base16 =
        (const __nv_bfloat162*)(g_encatt16 + (size_t)ord * PP * AA);
    for (int p = warp; p < PP; p += 16) {
        const __nv_bfloat162* row = base16 + (size_t)p * (AA/2);
        float acc = 0.f;
#pragma unroll
        for (int a2 = lane; a2 < AA/2; a2 += 32) {
            float2 f = __bfloat1622float2(row[a2]);
            int a = 2*a2;
            acc += fmaxf(f.x + s_hid[a],     0.f) * s_fw[a]
                 + fmaxf(f.y + s_hid[a + 1], 0.f) * s_fw[a + 1];
        }
        for (int o = 16; o; o >>= 1) acc += __shfl_xor_sync(0xFFFFFFFFu, acc, o);
        if (!lane) s_a[p] = acc;
    }
    __syncthreads();

    float v = (tid < PP) ? (s_a[tid] + fb[0]) : -1e30f;
    float m = v;
    for (int o = 16; o; o >>= 1) m = fmaxf(m, __shfl_xor_sync(0xFFFFFFFFu, m, o));
    if (!lane) s_r[warp] = m;
    __syncthreads();
    float bm = s_r[0];
    for (int i = 1; i < 16; i++) bm = fmaxf(bm, s_r[i]);
    __syncthreads();
    float ex = (tid < PP) ? expf(v - bm) : 0.f;
    float sm = ex;
    for (int o = 16; o; o >>= 1) sm += __shfl_xor_sync(0xFFFFFFFFu, sm, o);
    if (!lane) s_r[warp] = sm;
    __syncthreads();
    float bs = 0.f;
    for (int i = 0; i < 16; i++) bs += s_r[i];
    if (tid < PP) g_alpha[b*PP + tid] = ex / bs;
}

// ---------------- gated context (gs from fusedh partials inline) --------------
__global__ void ctx_kernel(int t)
{
    int b = blockIdx.y;
    if (g_predlen[b] <= t) return;
    __shared__ float s_a[PP];
    int tid = threadIdx.x;
    if (tid < PP) s_a[tid] = g_alpha[b*PP + tid];
    __syncthreads();

    int ord = g_order[b];
    int ch = blockIdx.x * 512 + tid * 2;
    const __nv_bfloat162* imgb =
        (const __nv_bfloat162*)(g_img16 + (size_t)ord * PP * ENC) + (ch >> 1);
    float a0 = 0.f, a1 = 0.f;
#pragma unroll 7
    for (int p = 0; p < PP; p++) {
        float2 f = __bfloat1622float2(imgb[(size_t)p * (ENC/2)]);
        float al = s_a[p];
        a0 = fmaf(al, f.x, a0);
        a1 = fmaf(al, f.y, a1);
    }
    size_t fo = (size_t)b*KG + AA + ch;
    float g0 = sigf(g_fhpart[0][fo]   + g_fhpart[1][fo]   + g_bias_fused[AA + ch]);
    float g1 = sigf(g_fhpart[0][fo+1] + g_fhpart[1][fo+1] + g_bias_fused[AA + ch + 1]);
    uint32_t hi, lo;
    cvt2(a0 * g0, a1 * g1, hi, lo);
    size_t off = ioff32(b, EE + ch, KGX);
    ((uint32_t*)g_gint)[off]             = hi;
    ((uint32_t*)g_gint)[(PE_GIN>>1)+off] = lo;
}

// ---------------- LSTM cell ----------------
__global__ void cell_kernel(int t)
{
    int b = blockIdx.x;
    if (g_predlen[b] <= t) return;
    int k = threadIdx.x * 2;
    size_t o = (size_t)b * 4*HH;
    float hv[2];
#pragma unroll
    for (int e = 0; e < 2; e++) {
        int j = k + e;
        float si = g_bias_gates[j],        sf = g_bias_gates[j + HH];
        float sg = g_bias_gates[j + 2*HH], so = g_bias_gates[j + 3*HH];
#pragma unroll
        for (int z = 0; z < NSPLITK; z++) {
            si += g_gpart[z][o + j];
            sf += g_gpart[z][o + j + HH];
            sg += g_gpart[z][o + j + 2*HH];
            so += g_gpart[z][o + j + 3*HH];
        }
        float ig = sigf(si), fg = sigf(sf), gg = tanhf(sg), og = sigf(so);
        float cc = fg * g_c[b*HH + j] + ig * gg;
        g_c[b*HH + j] = cc;
        hv[e] = og * tanhf(cc);
    }
    uint32_t hi, lo;
    cvt2(hv[0], hv[1], hi, lo);
    size_t oh = ioff32(b, k, HH);
    ((uint32_t*)g_himg)[oh]           = hi;
    ((uint32_t*)g_himg)[(PE_H>>1)+oh] = lo;
    size_t og2 = ioff32(b, k + KG, KGX);
    ((uint32_t*)g_gint)[og2]             = hi;
    ((uint32_t*)g_gint)[(PE_GIN>>1)+og2] = lo;
    size_t oa = ioff32(t*BB + b, k, HH);
    ((uint32_t*)g_hall)[oa]              = hi;
    ((uint32_t*)g_hall)[(PE_HALL>>1)+oa] = lo;
}

// ---------------- launch ----------------
extern "C" void kernel_launch(void* const* d_in, const int* in_sizes, int n_in,
                              void* d_out, int out_size)
{
    const float* img   = (const float*)d_in[0];
    const int*   caps  = (const int*)d_in[1];
    const int*   clen  = (const int*)d_in[2];
    const float* emb   = (const float*)d_in[3];
    const float* W_ih  = (const float*)d_in[4];
    const float* W_hh  = (const float*)d_in[5];
    const float* b_ih  = (const float*)d_in[6];
    const float* b_hh  = (const float*)d_in[7];
    const float* ec_w  = (const float*)d_in[8];
    const float* ec_b  = (const float*)d_in[9];
    const float* eh_w  = (const float*)d_in[10];
    const float* eh_b  = (const float*)d_in[11];
    const float* sag_w = (const float*)d_in[12];
    const float* sag_b = (const float*)d_in[13];
    const float* ae_w  = (const float*)d_in[14];
    const float* ae_b  = (const float*)d_in[15];
    const float* ah_w  = (const float*)d_in[16];
    const float* ah_b  = (const float*)d_in[17];
    const float* af_w  = (const float*)d_in[18];
    const float* af_b  = (const float*)d_in[19];
    const float* fc_w  = (const float*)d_in[20];
    const float* fc_b  = (const float*)d_in[21];
    float* out = (float*)d_out;

    float *p_c, *p_gpart, *p_fh;
    uint16_t *p_Wgt, *p_Whgt, *p_fct, *p_aet, *p_eht, *p_ect, *p_imgt, *p_meani,
             *p_himg, *p_gint, *p_hall;
    __nv_bfloat16 *p_ea16;
    cudaGetSymbolAddress((void**)&p_c,     g_c);
    cudaGetSymbolAddress((void**)&p_gpart, g_gpart);
    cudaGetSymbolAddress((void**)&p_fh,    g_fhpart);
    cudaGetSymbolAddress((void**)&p_Wgt,   g_Wgt);
    cudaGetSymbolAddress((void**)&p_Whgt,  g_Whgt);
    cudaGetSymbolAddress((void**)&p_fct,   g_fct);
    cudaGetSymbolAddress((void**)&p_aet,   g_aet);
    cudaGetSymbolAddress((void**)&p_eht,   g_eht);
    cudaGetSymbolAddress((void**)&p_ect,   g_ect);
    cudaGetSymbolAddress((void**)&p_imgt,  g_imgt);
    cudaGetSymbolAddress((void**)&p_meani, g_meani);
    cudaGetSymbolAddress((void**)&p_himg,  g_himg);
    cudaGetSymbolAddress((void**)&p_gint,  g_gint);
    cudaGetSymbolAddress((void**)&p_hall,  g_hall);
    cudaGetSymbolAddress((void**)&p_ea16,  g_encatt16);

    cudaFuncSetAttribute(kmma<false, true, M_PLAIN16, false>, cudaFuncAttributeMaxDynamicSharedMemorySize, SMEM_DYN);
    cudaFuncSetAttribute(kmma<true,  true, M_H0,      false>, cudaFuncAttributeMaxDynamicSharedMemorySize, SMEM_DYN);
    cudaFuncSetAttribute(kmma<true,  true, M_PLAIN,   false>, cudaFuncAttributeMaxDynamicSharedMemorySize, SMEM_DYN);
    cudaFuncSetAttribute(kmma<true,  true, M_PLAIN,   true >, cudaFuncAttributeMaxDynamicSharedMemorySize, SMEM_DYN);
    cudaFuncSetAttribute(kmma<true,  true, M_LOGB,    false>, cudaFuncAttributeMaxDynamicSharedMemorySize, SMEM_DYN);

    cudaMemsetAsync(d_out, 0, (size_t)out_size * sizeof(float));
    setup_kernel<<<1, 256>>>(caps, clen, b_ih, b_hh, ah_b, sag_b, out);
    build_all<<<GRID_BUILD, 256>>>(W_ih, W_hh, ah_w, sag_w, fc_w, ae_w, eh_w, ec_w, img);
    mean_kernel<<<dim3(ENC/512, BB), 256>>>(img);

    // enc_att precompute (hi*hi + hi*loW, bf16 out): M=50176, N=512, K=2048
    kmma<false, true, M_PLAIN16, false><<<dim3(AA/128, (BB*PP)/64), 256, SMEM_DYN>>>(
        p_imgt, ENC, PE_IMG, p_aet, ENC, PE_AE, ae_b, (float*)p_ea16, BB*PP, AA, ENC, 0);

    // h0 (-> h image + gatesin image), c0 (-> flat c)
    kmma<true, true, M_H0, false><<<dim3(HH/128, BB/64), 256, SMEM_DYN>>>(
        p_meani, ENC, PE_MEAN, p_eht, ENC, PE_EH, eh_b, nullptr, BB, HH, ENC, 0);
    kmma<true, true, M_PLAIN, false><<<dim3(HH/128, BB/64), 256, SMEM_DYN>>>(
        p_meani, ENC, PE_MEAN, p_ect, ENC, PE_EH, ec_b, p_c, BB, HH, ENC, 0);

    for (int t = 0; t < TT; t++) {
        // fused hid_att + gs, split-K=2 raw partials: M=256 N=2560 K=512
        kmma<true, true, M_PLAIN, true><<<dim3(KG/128, BB/64, 2), 256, SMEM_DYN>>>(
            p_himg, HH, PE_H, p_Whgt, HH, PE_WHG, nullptr, p_fh, BB, KG, HH/2, t);
        // attention scores + softmax (+ x_t gather; sums fh partials + bias)
        attn_kernel<<<BB, 512>>>(emb, af_w, af_b, t);
        // gated context (computes gs from fh partials inline)
        ctx_kernel<<<dim3(ENC/512, BB), 256>>>(t);
        // gates split-K=8: M=256 N=2048 K=3072 (Klen=384)
        kmma<true, true, M_PLAIN, true><<<dim3((4*HH)/128, BB/64, NSPLITK), 256, SMEM_DYN>>>(
            p_gint, KGX, PE_GIN, p_Wgt, KGX, PE_WG, nullptr, p_gpart, BB, 4*HH, KGX/NSPLITK, t);
        cell_kernel<<<BB, 256>>>(t);
    }

    // batched logits over all steps: M = TT*BB = 13568, N = 10112, K = 512
    kmma<true, true, M_LOGB, false><<<dim3(VVP/128, MALL/64), 256, SMEM_DYN>>>(
        p_hall, HH, PE_HALL, p_fct, HH, PE_FC, fc_b, out + OUT_PRED_OFF, MALL, VVP, HH, 0);
}

// round 17
// speedup vs baseline: 1.5275x; 1.0027x over previous
#include <cuda_runtime.h>
#include <cuda_bf16.h>
#include <cstdint>

#define BB   256
#define PP   196
#define ENC  2048
#define VV   10000
#define VVP  10112
#define EE   512
#define HH   512
#define AA   512
#define SS   54
#define TT   53
#define KG   2560
#define NG   2048                 // gates width (4*HH)
#define OUT_PRED_OFF (BB + BB*SS)
#define NSPLITK 8
#define STAGE_B 24576
#define SMEM_DYN (3*STAGE_B)
#define MALL (TT*BB)
#define NFHG (KG + NG)            // 4608

__device__ int   g_order[BB];
__device__ int   g_predlen[BB];
__device__ int   g_caps[BB*SS];
__device__ float g_bias_gates[NG];
__device__ float g_bias_fused[KG];
__device__ float g_c[BB*HH];
__device__ float g_alpha[BB*PP];
__device__ float g_gpart[NSPLITK][BB*NG];
__device__ float g_fhpart[2][(size_t)BB*KG];
__device__ float g_ghp[2][(size_t)BB*NG];

#define PE_WIX  ((size_t)NG*EE)
#define PE_WIC  ((size_t)NG*ENC)
#define PE_FHGW ((size_t)NFHG*HH)
#define PE_FC   ((size_t)VVP*HH)
#define PE_AE   ((size_t)AA*ENC)
#define PE_EH   ((size_t)HH*ENC)
#define PE_IMG  ((size_t)BB*PP*ENC)
#define PE_MEAN ((size_t)BB*ENC)
#define PE_H    ((size_t)BB*HH)
#define PE_GIN  ((size_t)BB*ENC)
#define PE_HALL ((size_t)MALL*HH)
#define PE_XA   ((size_t)MALL*EE)

__device__ __align__(128) uint16_t g_Wix  [2*PE_WIX];
__device__ __align__(128) uint16_t g_Wic  [2*PE_WIC];
__device__ __align__(128) uint16_t g_Wfhg [2*PE_FHGW];
__device__ __align__(128) uint16_t g_fct  [2*PE_FC];
__device__ __align__(128) uint16_t g_aet  [2*PE_AE];
__device__ __align__(128) uint16_t g_eht  [2*PE_EH];
__device__ __align__(128) uint16_t g_ect  [2*PE_EH];
__device__ __align__(128) uint16_t g_imgt [2*PE_IMG];   // lo plane unwritten
__device__ __align__(128) uint16_t g_meani[2*PE_MEAN];
__device__ __align__(128) uint16_t g_himg [2*PE_H];
__device__ __align__(128) uint16_t g_gint [2*PE_GIN];
__device__ __align__(128) uint16_t g_hall [2*PE_HALL];
__device__ __align__(128) uint16_t g_xa   [2*PE_XA];
__device__ float g_gx[(size_t)MALL*NG];
__device__ __align__(16)  __nv_bfloat16 g_img16[PE_IMG];
__device__ __align__(16)  __nv_bfloat16 g_encatt16[(size_t)BB*PP*AA];

__device__ __forceinline__ float sigf(float x) { return 1.f / (1.f + expf(-x)); }

__device__ __forceinline__ void cvt2(float x, float y, uint32_t& hi, uint32_t& lo) {
    __nv_bfloat162 h = __floats2bfloat162_rn(x, y);
    float rx = x - __bfloat162float(h.x);
    float ry = y - __bfloat162float(h.y);
    __nv_bfloat162 l = __floats2bfloat162_rn(rx, ry);
    hi = *(uint32_t*)&h;
    lo = *(uint32_t*)&l;
}

__device__ __forceinline__ size_t ioff32(int n, int k, int Kd) {
    return ((size_t)(n >> 3) * (Kd >> 3) + (k >> 3)) * 32 + (n & 7) * 4 + ((k & 7) >> 1);
}

__device__ __forceinline__ uint32_t smem_u32(const void* p) {
    uint32_t a;
    asm("{ .reg .u64 t; cvta.to.shared.u64 t, %1; cvt.u32.u64 %0, t; }" : "=r"(a) : "l"(p));
    return a;
}

__device__ __forceinline__ void mma_bf16(float4& d, const uint32_t a[4], const uint32_t b[2]) {
    asm volatile(
        "mma.sync.aligned.m16n8k16.row.col.f32.bf16.bf16.f32 "
        "{%0,%1,%2,%3}, {%4,%5,%6,%7}, {%8,%9}, {%0,%1,%2,%3};\n"
        : "+f"(d.x), "+f"(d.y), "+f"(d.z), "+f"(d.w)
        : "r"(a[0]), "r"(a[1]), "r"(a[2]), "r"(a[3]), "r"(b[0]), "r"(b[1]));
}

__device__ __forceinline__ void ldsm4(uint32_t r[4], uint32_t addr) {
    asm volatile("ldmatrix.sync.aligned.m8n8.x4.shared.b16 {%0,%1,%2,%3}, [%4];"
        : "=r"(r[0]), "=r"(r[1]), "=r"(r[2]), "=r"(r[3]) : "r"(addr));
}

// ---------------- setup ----------------
__global__ void setup_kernel(const int* __restrict__ caps32,
                             const int* __restrict__ lens32,
                             const float* __restrict__ b_ih,
                             const float* __restrict__ b_hh,
                             const float* __restrict__ ah_b,
                             const float* __restrict__ sag_b,
                             float* __restrict__ out)
{
    __shared__ int s_order[BB];
    __shared__ int s_is64;
    int tid = threadIdx.x;
    if (tid == 0) {
        int is64 = (lens32[1] == 0 && lens32[3] == 0 && lens32[5] == 0) ? 1 : 0;
        s_is64 = is64;
        int cnt[64];
        for (int i = 0; i < 64; i++) cnt[i] = 0;
        for (int i = 0; i < BB; i++) {
            int l = is64 ? lens32[2*i] : lens32[i];
            cnt[max(0, min(63, l))]++;
        }
        int start[64]; int run = 0;
        for (int l = 63; l >= 0; l--) { start[l] = run; run += cnt[l]; }
        for (int i = 0; i < BB; i++) {
            int l = is64 ? lens32[2*i] : lens32[i];
            s_order[start[max(0, min(63, l))]++] = i;
        }
    }
    __syncthreads();
    int is64 = s_is64;
    int b = tid;
    int ord = s_order[b];
    g_order[b] = ord;
    int len = is64 ? lens32[2*ord] : lens32[ord];
    len = max(1, min(SS, len));
    g_predlen[b] = len - 1;
    out[b] = (float)(len - 1);
    for (int s = 0; s < SS; s++) {
        size_t idx = (size_t)ord * SS + s;
        int cap = is64 ? caps32[2*idx] : caps32[idx];
        out[BB + b*SS + s] = (float)cap;
        g_caps[b*SS + s] = max(0, min(VV - 1, cap));
    }
    for (int j = tid; j < NG; j += BB) g_bias_gates[j] = b_ih[j] + b_hh[j];
    for (int j = tid; j < KG; j += BB)
        g_bias_fused[j] = (j < AA) ? ah_b[j] : sag_b[j - AA];
}

// ---------------- single build kernel: all weight + img images ----------------
#define GRID_BUILD 70528
__global__ void build_all(const float* __restrict__ W_ih, const float* __restrict__ W_hh,
                          const float* __restrict__ ah_w, const float* __restrict__ sag_w,
                          const float* __restrict__ fc_w, const float* __restrict__ ae_w,
                          const float* __restrict__ eh_w, const float* __restrict__ ec_w,
                          const float* __restrict__ img)
{
    int bid = blockIdx.x;
    const float* s = nullptr;
    uint16_t* dimg; size_t pe; int n, Ks, Kd; bool flat = false, wlo = true;

    if (bid < 2048)       { s = W_ih + (size_t)bid*KG;        dimg = g_Wix;  pe = PE_WIX;  n = bid;        Ks = EE;   Kd = EE;  }
    else if (bid < 4096)  { int i = bid-2048;  s = W_ih + (size_t)i*KG + EE; dimg = g_Wic;  pe = PE_WIC;  n = i;       Ks = ENC;  Kd = ENC; }
    else if (bid < 4608)  { int i = bid-4096;  s = ah_w + (size_t)i*HH;      dimg = g_Wfhg; pe = PE_FHGW; n = i;       Ks = HH;   Kd = HH;  }
    else if (bid < 6656)  { int i = bid-4608;  s = sag_w + (size_t)i*HH;     dimg = g_Wfhg; pe = PE_FHGW; n = AA+i;    Ks = HH;   Kd = HH;  }
    else if (bid < 8704)  { int i = bid-6656;  s = W_hh + (size_t)i*HH;      dimg = g_Wfhg; pe = PE_FHGW; n = KG+i;    Ks = HH;   Kd = HH;  }
    else if (bid < 18704) { int i = bid-8704;  s = fc_w + (size_t)i*HH;      dimg = g_fct;  pe = PE_FC;   n = i;       Ks = HH;   Kd = HH;  }
    else if (bid < 18816) { int i = bid-18704; s = nullptr;                   dimg = g_fct;  pe = PE_FC;   n = VV+i;    Ks = HH;   Kd = HH;  }
    else if (bid < 19328) { int i = bid-18816; s = ae_w + (size_t)i*ENC;     dimg = g_aet;  pe = PE_AE;   n = i;       Ks = ENC;  Kd = ENC; }
    else if (bid < 19840) { int i = bid-19328; s = eh_w + (size_t)i*ENC;     dimg = g_eht;  pe = PE_EH;   n = i;       Ks = ENC;  Kd = ENC; }
    else if (bid < 20352) { int i = bid-19840; s = ec_w + (size_t)i*ENC;     dimg = g_ect;  pe = PE_EH;   n = i;       Ks = ENC;  Kd = ENC; }
    else                  { int i = bid-20352; s = img + (size_t)i*ENC;      dimg = g_imgt; pe = PE_IMG;  n = i;       Ks = ENC;  Kd = ENC; flat = true; wlo = false; }

    uint32_t* d32 = (uint32_t*)dimg;
    size_t p32 = pe >> 1;
    for (int p = threadIdx.x; p < Ks/2; p += 256) {
        int k = 2*p;
        float v0 = 0.f, v1 = 0.f;
        if (s) { float2 vv = *(const float2*)(s + k); v0 = vv.x; v1 = vv.y; }
        uint32_t hi, lo;
        cvt2(v0, v1, hi, lo);
        size_t off = ioff32(n, k, Kd);
        d32[off] = hi;
        if (wlo) d32[p32 + off] = lo;
        if (flat) ((uint32_t*)g_img16)[((size_t)n*ENC + k) >> 1] = hi;
    }
}

// ---------------- x images for all steps ----------------
__global__ void build_xall(const float* __restrict__ emb)
{
    int m = blockIdx.x;              // t*BB + b
    int b = m & 255, t = m >> 8;
    int cap = g_caps[b*SS + t];
    float2 v = ((const float2*)(emb + (size_t)cap * EE))[threadIdx.x];
    uint32_t hi, lo;
    cvt2(v.x, v.y, hi, lo);
    size_t off = ioff32(m, threadIdx.x * 2, EE);
    ((uint32_t*)g_xa)[off]             = hi;
    ((uint32_t*)g_xa)[(PE_XA>>1)+off]  = lo;
}

// ---------------- mean over pixels -> tiled mean image ----------------
__global__ void mean_kernel(const float* __restrict__ img)
{
    int b  = blockIdx.y;
    int ch = (blockIdx.x * 256 + threadIdx.x) * 2;
    int ord = g_order[b];
    const float2* base = (const float2*)(img + (size_t)ord * PP * ENC) + (ch >> 1);
    float a0 = 0.f, a1 = 0.f;
#pragma unroll 4
    for (int p = 0; p < PP; p++) { float2 v = base[(size_t)p * (ENC/2)]; a0 += v.x; a1 += v.y; }
    a0 *= (1.0f / (float)PP);
    a1 *= (1.0f / (float)PP);
    uint32_t hi, lo;
    cvt2(a0, a1, hi, lo);
    size_t off = ioff32(b, ch, ENC);
    ((uint32_t*)g_meani)[off]             = hi;
    ((uint32_t*)g_meani)[(PE_MEAN>>1)+off]= lo;
}

// ================= bf16 HMMA GEMM: plane-flagged decomposition ==========
#define M_PLAIN   0
#define M_LOGB    2
#define M_PLAIN16 3
#define M_H0      4
#define M_FHG     5
#define M_BXP     6

template<bool ALO, bool WLO, int MODE, bool MASKED>
__global__ void __launch_bounds__(256)
kmma(const uint16_t* __restrict__ At, int Ka, size_t pA,
     const uint16_t* __restrict__ Wt, int Kw, size_t pW,
     const float* __restrict__ bias, float* __restrict__ C,
     int M, int N, int Klen, int t)
{
    extern __shared__ __align__(16) char smd[];
    const int m0 = blockIdx.y * 64;
    const int n0 = blockIdx.x * 128;
    if (MASKED && g_predlen[m0] <= t) return;
    if (MODE == M_LOGB || MODE == M_BXP) {
        if (g_predlen[m0 & 255] <= (m0 >> 8)) return;
    }
    const int kbase = blockIdx.z * Klen;
    if (gridDim.z > 1 && MODE != M_FHG) C += (size_t)blockIdx.z * M * N;

    const int tid  = threadIdx.x;
    const int lane = tid & 31;
    const int w    = tid >> 5;
    const int wm   = (w & 1) * 32;
    const int wn   = (w >> 1) * 32;
    const int r    = lane >> 2;
    const int c    = lane & 3;
    const int g8   = lane >> 3;
    const int r8   = lane & 7;
    const uint32_t sbase = smem_u32(smd);

    const int a_mt = tid >> 5, a_kt = (tid >> 3) & 3, a_rw = tid & 7;

    float4 acc[2][4];
#pragma unroll
    for (int i = 0; i < 2; i++)
#pragma unroll
        for (int j = 0; j < 4; j++) acc[i][j] = make_float4(0.f, 0.f, 0.f, 0.f);

    auto fill = [&](int s, int buf) {
        int k0 = kbase + s * 32;
        uint32_t sreg = sbase + (uint32_t)buf * STAGE_B;
        {
            size_t tile = (size_t)((m0 >> 3) + a_mt) * (Ka >> 3) + ((k0 >> 3) + a_kt);
            uint32_t so = sreg + (uint32_t)((a_mt * 4 + a_kt) * 128 + a_rw * 16);
            const char* g = (const char*)At + tile * 128 + a_rw * 16;
            asm volatile("cp.async.cg.shared.global [%0], [%1], 16;" :: "r"(so), "l"(g));
            if (ALO)
                asm volatile("cp.async.cg.shared.global [%0], [%1], 16;"
                             :: "r"(so + 4096), "l"(g + pA * 2));
        }
#pragma unroll
        for (int i = 0; i < (WLO ? 4 : 2); i++) {
            int plane = i >> 1, half = i & 1;
            int uu = tid + half * 256;
            int nt = uu >> 5, kt = (uu >> 3) & 3, rw = uu & 7;
            size_t tile = (size_t)((n0 >> 3) + nt) * (Kw >> 3) + ((k0 >> 3) + kt);
            const char* g = (const char*)Wt + (size_t)plane * pW * 2 + tile * 128 + rw * 16;
            uint32_t so = sreg + 8192 + (uint32_t)(plane * 8192 + (nt * 4 + kt) * 128 + rw * 16);
            asm volatile("cp.async.cg.shared.global [%0], [%1], 16;" :: "r"(so), "l"(g));
        }
        asm volatile("cp.async.commit_group;" ::: "memory");
    };

    const int nst = Klen / 32;
    fill(0, 0);
    fill(1, 1);
    for (int s = 0; s < nst; s++) {
        if (s + 1 < nst) asm volatile("cp.async.wait_group 1;" ::: "memory");
        else             asm volatile("cp.async.wait_group 0;" ::: "memory");
        __syncthreads();
        if (s + 2 < nst) fill(s + 2, (s + 2) % 3);

        uint32_t st = sbase + (uint32_t)(s % 3) * STAGE_B;
#pragma unroll
        for (int kk = 0; kk < 2; kk++) {
            uint32_t ah[2][4], al[2][4], bh[4][2], bl[4][2];
#pragma unroll
            for (int ms = 0; ms < 2; ms++) {
                int mtb = (wm >> 3) + ms * 2;
                uint32_t ad = st + (uint32_t)((mtb + (g8 & 1)) * 4 + 2*kk + (g8 >> 1)) * 128 + r8 * 16;
                ldsm4(ah[ms], ad);
                if (ALO) ldsm4(al[ms], ad + 4096);
            }
#pragma unroll
            for (int np = 0; np < 2; np++) {
                int ntb = (wn >> 3) + np * 2;
                uint32_t wd = st + 8192 + (uint32_t)((ntb + (g8 >> 1)) * 4 + 2*kk + (g8 & 1)) * 128 + r8 * 16;
                uint32_t tmp[4];
                ldsm4(tmp, wd);
                bh[2*np][0] = tmp[0]; bh[2*np][1] = tmp[1];
                bh[2*np+1][0] = tmp[2]; bh[2*np+1][1] = tmp[3];
                if (WLO) {
                    ldsm4(tmp, wd + 8192);
                    bl[2*np][0] = tmp[0]; bl[2*np][1] = tmp[1];
                    bl[2*np+1][0] = tmp[2]; bl[2*np+1][1] = tmp[3];
                }
            }
#pragma unroll
            for (int ms = 0; ms < 2; ms++)
#pragma unroll
                for (int ns = 0; ns < 4; ns++) {
                    mma_bf16(acc[ms][ns], ah[ms], bh[ns]);
                    if (ALO) mma_bf16(acc[ms][ns], al[ms], bh[ns]);
                    if (WLO) mma_bf16(acc[ms][ns], ah[ms], bl[ns]);
                }
        }
    }

    // ---- epilogue ----
    auto wpair_h0 = [&](int row, int col, float x, float y) {
        uint32_t hi, lo;
        cvt2(x, y, hi, lo);
        size_t oh = ioff32(row, col, HH);
        ((uint32_t*)g_himg)[oh]           = hi;
        ((uint32_t*)g_himg)[(PE_H>>1)+oh] = lo;
    };
    auto epi1 = [&](int m, int n, float v) {
        if (n >= N) return;
        if (MODE == M_PLAIN || MODE == M_BXP) {
            C[(size_t)m * N + n] = v;
        } else if (MODE == M_PLAIN16) {
            ((__nv_bfloat16*)C)[(size_t)m * N + n] = __float2bfloat16(v);
        } else if (MODE == M_LOGB) {
            int bb = m & 255, tt = m >> 8;
            if (n < VV && g_predlen[bb] > tt)
                C[((size_t)bb * TT + tt) * VV + n] = v;
        } else if (MODE == M_FHG) {
            int z = blockIdx.z;
            if (n < KG) g_fhpart[z][(size_t)m * KG + n] = v;
            else        g_ghp[z][(size_t)m * NG + (n - KG)] = v;
        }
    };

#pragma unroll
    for (int ms = 0; ms < 2; ms++)
#pragma unroll
        for (int ns = 0; ns < 4; ns++) {
            int row = m0 + wm + ms*16 + r;
            int col = n0 + wn + ns*8 + 2*c;
            float4 d = acc[ms][ns];
            float bx = 0.f, by = 0.f;
            if (bias && col < N)     bx = bias[col];
            if (bias && col + 1 < N) by = bias[col + 1];
            float vx = d.x + bx, vy = d.y + by;
            float vz = d.z + bx, vw = d.w + by;
            if (MODE == M_H0) {
                wpair_h0(row,     col, vx, vy);
                wpair_h0(row + 8, col, vz, vw);
            } else {
                epi1(row,     col,     vx);
                epi1(row,     col + 1, vy);
                epi1(row + 8, col,     vz);
                epi1(row + 8, col + 1, vw);
            }
        }
}

// ---------------- attention: scores + softmax (512 thr) ----------
__global__ void attn_kernel(const float* __restrict__ fw,
                            const float* __restrict__ fb, int t)
{
    int b = blockIdx.x;
    if (g_predlen[b] <= t) return;
    __shared__ float s_fw[AA], s_hid[AA], s_a[200], s_r[16];
    int tid = threadIdx.x;

    s_fw[tid]  = fw[tid];
    s_hid[tid] = g_fhpart[0][(size_t)b*KG + tid] + g_fhpart[1][(size_t)b*KG + tid]
               + g_bias_fused[tid];
    __syncthreads();

    int warp = tid >> 5, lane = tid & 31;
    int ord = g_order[b];
    const __nv_bfloat162* base16 =
        (const __nv_bfloat162*)(g_encatt16 + (size_t)ord * PP * AA);
    for (int p = warp; p < PP; p += 16) {
        const __nv_bfloat162* row = base16 + (size_t)p * (AA/2);
        float acc = 0.f;
#pragma unroll
        for (int a2 = lane; a2 < AA/2; a2 += 32) {
            float2 f = __bfloat1622float2(row[a2]);
            int a = 2*a2;
            acc += fmaxf(f.x + s_hid[a],     0.f) * s_fw[a]
                 + fmaxf(f.y + s_hid[a + 1], 0.f) * s_fw[a + 1];
        }
        for (int o = 16; o; o >>= 1) acc += __shfl_xor_sync(0xFFFFFFFFu, acc, o);
        if (!lane) s_a[p] = acc;
    }
    __syncthreads();

    float v = (tid < PP) ? (s_a[tid] + fb[0]) : -1e30f;
    float m = v;
    for (int o = 16; o; o >>= 1) m = fmaxf(m, __shfl_xor_sync(0xFFFFFFFFu, m, o));
    if (!lane) s_r[warp] = m;
    __syncthreads();
    float bm = s_r[0];
    for (int i = 1; i < 16; i++) bm = fmaxf(bm, s_r[i]);
    __syncthreads();
    float ex = (tid < PP) ? expf(v - bm) : 0.f;
    float sm = ex;
    for (int o = 16; o; o >>= 1) sm += __shfl_xor_sync(0xFFFFFFFFu, sm, o);
    if (!lane) s_r[warp] = sm;
    __syncthreads();
    float bs = 0.f;
    for (int i = 0; i < 16; i++) bs += s_r[i];
    if (tid < PP) g_alpha[b*PP + tid] = ex / bs;
}

// ---------------- gated context -> ctx image (K=2048) --------------
__global__ void ctx_kernel(int t)
{
    int b = blockIdx.y;
    if (g_predlen[b] <= t) return;
    __shared__ float s_a[PP];
    int tid = threadIdx.x;
    if (tid < PP) s_a[tid] = g_alpha[b*PP + tid];
    __syncthreads();

    int ord = g_order[b];
    int ch = blockIdx.x * 512 + tid * 2;
    const __nv_bfloat162* imgb =
        (const __nv_bfloat162*)(g_img16 + (size_t)ord * PP * ENC) + (ch >> 1);
    float a0 = 0.f, a1 = 0.f;
#pragma unroll 7
    for (int p = 0; p < PP; p++) {
        float2 f = __bfloat1622float2(imgb[(size_t)p * (ENC/2)]);
        float al = s_a[p];
        a0 = fmaf(al, f.x, a0);
        a1 = fmaf(al, f.y, a1);
    }
    size_t fo = (size_t)b*KG + AA + ch;
    float g0 = sigf(g_fhpart[0][fo]   + g_fhpart[1][fo]   + g_bias_fused[AA + ch]);
    float g1 = sigf(g_fhpart[0][fo+1] + g_fhpart[1][fo+1] + g_bias_fused[AA + ch + 1]);
    uint32_t hi, lo;
    cvt2(a0 * g0, a1 * g1, hi, lo);
    size_t off = ioff32(b, ch, ENC);
    ((uint32_t*)g_gint)[off]             = hi;
    ((uint32_t*)g_gint)[(PE_GIN>>1)+off] = lo;
}

// ---------------- LSTM cell ----------------
__global__ void cell_kernel(int t)
{
    int b = blockIdx.x;
    if (g_predlen[b] <= t) return;
    int k = threadIdx.x * 2;
    size_t o  = (size_t)b * NG;
    size_t ox = ((size_t)t * BB + b) * NG;
    float hv[2];
#pragma unroll
    for (int e = 0; e < 2; e++) {
        int j = k + e;
        float si = g_bias_gates[j]         + g_gx[ox + j];
        float sf = g_bias_gates[j + HH]    + g_gx[ox + j + HH];
        float sg = g_bias_gates[j + 2*HH]  + g_gx[ox + j + 2*HH];
        float so = g_bias_gates[j + 3*HH]  + g_gx[ox + j + 3*HH];
#pragma unroll
        for (int z = 0; z < NSPLITK; z++) {
            si += g_gpart[z][o + j];
            sf += g_gpart[z][o + j + HH];
            sg += g_gpart[z][o + j + 2*HH];
            so += g_gpart[z][o + j + 3*HH];
        }
#pragma unroll
        for (int z = 0; z < 2; z++) {
            si += g_ghp[z][o + j];
            sf += g_ghp[z][o + j + HH];
            sg += g_ghp[z][o + j + 2*HH];
            so += g_ghp[z][o + j + 3*HH];
        }
        float ig = sigf(si), fg = sigf(sf), gg = tanhf(sg), og = sigf(so);
        float cc = fg * g_c[b*HH + j] + ig * gg;
        g_c[b*HH + j] = cc;
        hv[e] = og * tanhf(cc);
    }
    uint32_t hi, lo;
    cvt2(hv[0], hv[1], hi, lo);
    size_t oh = ioff32(b, k, HH);
    ((uint32_t*)g_himg)[oh]           = hi;
    ((uint32_t*)g_himg)[(PE_H>>1)+oh] = lo;
    size_t oa = ioff32(t*BB + b, k, HH);
    ((uint32_t*)g_hall)[oa]              = hi;
    ((uint32_t*)g_hall)[(PE_HALL>>1)+oa] = lo;
}

// ---------------- launch ----------------
extern "C" void kernel_launch(void* const* d_in, const int* in_sizes, int n_in,
                              void* d_out, int out_size)
{
    const float* img   = (const float*)d_in[0];
    const int*   caps  = (const int*)d_in[1];
    const int*   clen  = (const int*)d_in[2];
    const float* emb   = (const float*)d_in[3];
    const float* W_ih  = (const float*)d_in[4];
    const float* W_hh  = (const float*)d_in[5];
    const float* b_ih  = (const float*)d_in[6];
    const float* b_hh  = (const float*)d_in[7];
    const float* ec_w  = (const float*)d_in[8];
    const float* ec_b  = (const float*)d_in[9];
    const float* eh_w  = (const float*)d_in[10];
    const float* eh_b  = (const float*)d_in[11];
    const float* sag_w = (const float*)d_in[12];
    const float* sag_b = (const float*)d_in[13];
    const float* ae_w  = (const float*)d_in[14];
    const float* ae_b  = (const float*)d_in[15];
    const float* ah_w  = (const float*)d_in[16];
    const float* ah_b  = (const float*)d_in[17];
    const float* af_w  = (const float*)d_in[18];
    const float* af_b  = (const float*)d_in[19];
    const float* fc_w  = (const float*)d_in[20];
    const float* fc_b  = (const float*)d_in[21];
    float* out = (float*)d_out;

    float *p_c, *p_gpart, *p_gx;
    uint16_t *p_Wix, *p_Wic, *p_Wfhg, *p_fct, *p_aet, *p_eht, *p_ect, *p_imgt,
             *p_meani, *p_himg, *p_gint, *p_hall, *p_xa;
    __nv_bfloat16 *p_ea16;
    cudaGetSymbolAddress((void**)&p_c,     g_c);
    cudaGetSymbolAddress((void**)&p_gpart, g_gpart);
    cudaGetSymbolAddress((void**)&p_gx,    g_gx);
    cudaGetSymbolAddress((void**)&p_Wix,   g_Wix);
    cudaGetSymbolAddress((void**)&p_Wic,   g_Wic);
    cudaGetSymbolAddress((void**)&p_Wfhg,  g_Wfhg);
    cudaGetSymbolAddress((void**)&p_fct,   g_fct);
    cudaGetSymbolAddress((void**)&p_aet,   g_aet);
    cudaGetSymbolAddress((void**)&p_eht,   g_eht);
    cudaGetSymbolAddress((void**)&p_ect,   g_ect);
    cudaGetSymbolAddress((void**)&p_imgt,  g_imgt);
    cudaGetSymbolAddress((void**)&p_meani, g_meani);
    cudaGetSymbolAddress((void**)&p_himg,  g_himg);
    cudaGetSymbolAddress((void**)&p_gint,  g_gint);
    cudaGetSymbolAddress((void**)&p_hall,  g_hall);
    cudaGetSymbolAddress((void**)&p_xa,    g_xa);
    cudaGetSymbolAddress((void**)&p_ea16,  g_encatt16);

    cudaFuncSetAttribute(kmma<false, true, M_PLAIN16, false>, cudaFuncAttributeMaxDynamicSharedMemorySize, SMEM_DYN);
    cudaFuncSetAttribute(kmma<true,  true, M_H0,      false>, cudaFuncAttributeMaxDynamicSharedMemorySize, SMEM_DYN);
    cudaFuncSetAttribute(kmma<true,  true, M_PLAIN,   false>, cudaFuncAttributeMaxDynamicSharedMemorySize, SMEM_DYN);
    cudaFuncSetAttribute(kmma<true,  true, M_PLAIN,   true >, cudaFuncAttributeMaxDynamicSharedMemorySize, SMEM_DYN);
    cudaFuncSetAttribute(kmma<true,  true, M_FHG,     true >, cudaFuncAttributeMaxDynamicSharedMemorySize, SMEM_DYN);
    cudaFuncSetAttribute(kmma<true,  true, M_BXP,     false>, cudaFuncAttributeMaxDynamicSharedMemorySize, SMEM_DYN);
    cudaFuncSetAttribute(kmma<true,  true, M_LOGB,    false>, cudaFuncAttributeMaxDynamicSharedMemorySize, SMEM_DYN);

    cudaMemsetAsync(d_out, 0, (size_t)out_size * sizeof(float));
    setup_kernel<<<1, 256>>>(caps, clen, b_ih, b_hh, ah_b, sag_b, out);
    build_all<<<GRID_BUILD, 256>>>(W_ih, W_hh, ah_w, sag_w, fc_w, ae_w, eh_w, ec_w, img);
    build_xall<<<MALL, 256>>>(emb);
    mean_kernel<<<dim3(ENC/512, BB), 256>>>(img);

    // enc_att precompute (hi*hi + hi*loW, bf16 out): M=50176, N=512, K=2048
    kmma<false, true, M_PLAIN16, false><<<dim3(AA/128, (BB*PP)/64), 256, SMEM_DYN>>>(
        p_imgt, ENC, PE_IMG, p_aet, ENC, PE_AE, ae_b, (float*)p_ea16, BB*PP, AA, ENC, 0);

    // batched x-part of gates: M=13568, N=2048, K=512 (raw, no bias)
    kmma<true, true, M_BXP, false><<<dim3(NG/128, MALL/64), 256, SMEM_DYN>>>(
        p_xa, EE, PE_XA, p_Wix, EE, PE_WIX, nullptr, p_gx, MALL, NG, EE, 0);

    // h0 (-> h image), c0 (-> flat c)
    kmma<true, true, M_H0, false><<<dim3(HH/128, BB/64), 256, SMEM_DYN>>>(
        p_meani, ENC, PE_MEAN, p_eht, ENC, PE_EH, eh_b, nullptr, BB, HH, ENC, 0);
    kmma<true, true, M_PLAIN, false><<<dim3(HH/128, BB/64), 256, SMEM_DYN>>>(
        p_meani, ENC, PE_MEAN, p_ect, ENC, PE_EH, ec_b, p_c, BB, HH, ENC, 0);

    for (int t = 0; t < TT; t++) {
        // merged h-GEMM: hid_att + gs + gates-h, split-K=2: M=256 N=4608 K=512
        kmma<true, true, M_FHG, true><<<dim3(NFHG/128, BB/64, 2), 256, SMEM_DYN>>>(
            p_himg, HH, PE_H, p_Wfhg, HH, PE_FHGW, nullptr, nullptr, BB, NFHG, HH/2, t);
        // attention scores + softmax (sums fh partials + bias)
        attn_kernel<<<BB, 512>>>(af_w, af_b, t);
        // gated context (gs inline) -> ctx image
        ctx_kernel<<<dim3(ENC/512, BB), 256>>>(t);
        // gates ctx-part split-K=8: M=256 N=2048 K=2048 (Klen=256)
        kmma<true, true, M_PLAIN, true><<<dim3(NG/128, BB/64, NSPLITK), 256, SMEM_DYN>>>(
            p_gint, ENC, PE_GIN, p_Wic, ENC, PE_WIC, nullptr, p_gpart, BB, NG, ENC/NSPLITK, t);
        cell_kernel<<<BB, 256>>>(t);
    }

    // batched logits over all steps: M = 13568, N = 10112, K = 512
    kmma<true, true, M_LOGB, false><<<dim3(VVP/128, MALL/64), 256, SMEM_DYN>>>(
        p_hall, HH, PE_HALL, p_fct, HH, PE_FC, fc_b, out + OUT_PRED_OFF, MALL, VVP, HH, 0);
}